// round 6
// baseline (speedup 1.0000x reference)
#include <cuda_runtime.h>

// Problem constants
#define NB   64
#define NT   1025      // tokens = 1024 patches + cls
#define ND   256       // token dim
#define NH   1024      // FFN hidden
#define NCLS 1000

// ---------------- static scratch (no allocations allowed) ----------------
__device__ float g_t  [64LL*1025*256];
__device__ float g_h  [64LL*1025*256];
__device__ float g_U  [64LL*1025*256];
__device__ float g_V  [64LL*1025*256];
__device__ float g_hid[64LL*1025*1024];
__device__ float g_Cd[256*256];
__device__ float g_Sd[256*256];
__device__ float g_Cn[1025LL*1025];
__device__ float g_Sn[1025LL*1025];
__device__ float g_wT[768*256];
__device__ float g_pooled[64*256];

// ---------------- small helpers ----------------
__device__ __forceinline__ float warp_sum(float v) {
#pragma unroll
    for (int o = 16; o > 0; o >>= 1) v += __shfl_xor_sync(0xffffffffu, v, o);
    return v;
}
__device__ __forceinline__ float warp_max(float v) {
#pragma unroll
    for (int o = 16; o > 0; o >>= 1) v = fmaxf(v, __shfl_xor_sync(0xffffffffu, v, o));
    return v;
}
// blockDim.x == 256 assumed
__device__ float block_sum(float v, float* sbuf) {
    int tid = threadIdx.x;
    float w = warp_sum(v);
    if ((tid & 31) == 0) sbuf[tid >> 5] = w;
    __syncthreads();
    float r = (tid < 8) ? sbuf[tid] : 0.f;
    if (tid < 32) { r = warp_sum(r); if (tid == 0) sbuf[0] = r; }
    __syncthreads();
    float res = sbuf[0];
    __syncthreads();
    return res;
}
__device__ float block_max(float v, float* sbuf) {
    int tid = threadIdx.x;
    float w = warp_max(v);
    if ((tid & 31) == 0) sbuf[tid >> 5] = w;
    __syncthreads();
    float r = (tid < 8) ? sbuf[tid] : -3.4e38f;
    if (tid < 32) { r = warp_max(r); if (tid == 0) sbuf[0] = r; }
    __syncthreads();
    float res = sbuf[0];
    __syncthreads();
    return res;
}

// ---------------- DFT matrix fill (exact integer phase reduction) ----------------
__global__ void fill_dft_d() {
    int i = blockIdx.x, j = threadIdx.x;
    int r = (i * j) % ND;
    float s, c;
    sincospif(2.0f * (float)r / (float)ND, &s, &c);
    g_Cd[i * ND + j] = c;
    g_Sd[i * ND + j] = s;
}
__global__ void fill_dft_n() {
    int i = blockIdx.x;
    for (int j = threadIdx.x; j < NT; j += 256) {
        int r = (int)(((long long)i * (long long)j) % NT);
        float s, c;
        sincospif(2.0f * (float)r / (float)NT, &s, &c);
        g_Cn[(long long)i * NT + j] = c;
        g_Sn[(long long)i * NT + j] = s;
    }
}

// ---------------- weight transpose: conv_w (256,768) -> wT (768,256) ----------------
__global__ void transpose_w(const float* __restrict__ w) {
    int k = blockIdx.x;      // 0..767
    int d = threadIdx.x;     // 0..255
    g_wT[k * ND + d] = w[(long long)d * 768 + k];
}

// ---------------- patch embed: tok[b,p,d] = sum_k patch[k]*w[d,k] ----------------
// grid (128, 64), block 256. 8 patches per block.
__global__ void patch_embed(const float* __restrict__ x) {
    __shared__ float sp[8][768];
    int b  = blockIdx.y;
    int p0 = blockIdx.x * 8;
    int tid = threadIdx.x;
    for (int i = tid; i < 8 * 768; i += 256) {
        int pi = i / 768, k = i % 768;
        int p = p0 + pi;
        int gh = p >> 5, gw = p & 31;
        int c = k >> 8, rem = k & 255, r = rem >> 4, q = rem & 15;
        sp[pi][k] = x[(((long long)b * 3 + c) * 512 + gh * 16 + r) * 512 + gw * 16 + q];
    }
    __syncthreads();
    float acc[8] = {0.f,0.f,0.f,0.f,0.f,0.f,0.f,0.f};
    int d = tid;
#pragma unroll 4
    for (int k = 0; k < 768; k++) {
        float w = g_wT[k * ND + d];
#pragma unroll
        for (int pi = 0; pi < 8; pi++) acc[pi] = fmaf(sp[pi][k], w, acc[pi]);
    }
#pragma unroll
    for (int pi = 0; pi < 8; pi++) {
        int p = p0 + pi;
        g_t[((long long)b * NT + 1 + p) * ND + d] = acc[pi];
    }
}

// ---------------- assemble: cls token, pos emb, conv bias ----------------
// grid (1025, 64), block 256
__global__ void assemble(const float* __restrict__ conv_b,
                         const float* __restrict__ pos,
                         const float* __restrict__ cls) {
    int n = blockIdx.x, b = blockIdx.y, d = threadIdx.x;
    long long off = ((long long)b * NT + n) * ND + d;
    if (n == 0) g_t[off] = cls[d] + pos[d];
    else        g_t[off] += conv_b[d] + pos[(long long)n * ND + d];
}

// ---------------- layernorm over last dim (256), one row per block ----------------
__global__ void ln_kernel(const float* __restrict__ in, float* __restrict__ out,
                          const float* __restrict__ gam, const float* __restrict__ bet) {
    __shared__ float sbuf[32];
    long long row = blockIdx.x;
    int tid = threadIdx.x;
    float v = in[row * ND + tid];
    float mean = block_sum(v, sbuf) * (1.f / 256.f);
    float d = v - mean;
    float var = block_sum(d * d, sbuf) * (1.f / 256.f);
    out[row * ND + tid] = d * rsqrtf(var + 1e-5f) * gam[tid] + bet[tid];
}

// ---------------- fused dual GEMM: U = h*Cd, V = h*Sd ----------------
// M=65600, K=256, N=256 (all tile-exact). grid (4, 1025), block 256.
__global__ void dft_gemm() {
    __shared__ float As[16][68], B1s[16][68], B2s[16][68];
    int tid = threadIdx.x;
    int tx = tid & 15, ty = tid >> 4;
    int m0 = blockIdx.y << 6, n0 = blockIdx.x << 6;
    int arow = tid >> 2, acol = (tid & 3) << 2;
    int brow = tid >> 4, bcol = (tid & 15) << 2;
    float acc1[4][4] = {}, acc2[4][4] = {};
    for (int k0 = 0; k0 < ND; k0 += 16) {
        float4 av = *(const float4*)&g_h[(long long)(m0 + arow) * ND + k0 + acol];
        As[acol + 0][arow] = av.x; As[acol + 1][arow] = av.y;
        As[acol + 2][arow] = av.z; As[acol + 3][arow] = av.w;
        int kb = k0 + brow;
        *(float4*)&B1s[brow][bcol] = *(const float4*)&g_Cd[kb * ND + n0 + bcol];
        *(float4*)&B2s[brow][bcol] = *(const float4*)&g_Sd[kb * ND + n0 + bcol];
        __syncthreads();
#pragma unroll
        for (int k = 0; k < 16; k++) {
            float4 a  = *(const float4*)&As[k][ty << 2];
            float4 b1 = *(const float4*)&B1s[k][tx << 2];
            float4 b2 = *(const float4*)&B2s[k][tx << 2];
            float ar[4] = {a.x, a.y, a.z, a.w};
            float c1[4] = {b1.x, b1.y, b1.z, b1.w};
            float c2[4] = {b2.x, b2.y, b2.z, b2.w};
#pragma unroll
            for (int i = 0; i < 4; i++)
#pragma unroll
                for (int j = 0; j < 4; j++) {
                    acc1[i][j] = fmaf(ar[i], c1[j], acc1[i][j]);
                    acc2[i][j] = fmaf(ar[i], c2[j], acc2[i][j]);
                }
        }
        __syncthreads();
    }
#pragma unroll
    for (int i = 0; i < 4; i++) {
        long long row = m0 + (ty << 2) + i;
#pragma unroll
        for (int j = 0; j < 4; j++) {
            long long off = row * ND + n0 + (tx << 2) + j;
            g_U[off] = acc1[i][j];
            g_V[off] = acc2[i][j];
        }
    }
}

// ---------------- fused mixing GEMM: t += Cn*U - Sn*V (per batch) ----------------
// grid (4, 17, 64), block 256. M=K=1025 (guarded), N=256.
__global__ void mix_gemm() {
    __shared__ float A1s[16][68], A2s[16][68], B1s[16][68], B2s[16][68];
    int tid = threadIdx.x;
    int tx = tid & 15, ty = tid >> 4;
    int m0 = blockIdx.y << 6, n0 = blockIdx.x << 6;
    long long base = (long long)blockIdx.z * NT * ND;
    int arow = tid >> 2, acol = (tid & 3) << 2;
    int brow = tid >> 4, bcol = (tid & 15) << 2;
    float acc[4][4] = {};
    int m = m0 + arow;
    for (int k0 = 0; k0 < NT; k0 += 16) {
#pragma unroll
        for (int tt = 0; tt < 4; tt++) {
            int k = k0 + acol + tt;
            bool ok = (m < NT) && (k < NT);
            long long ai = (long long)m * NT + k;
            A1s[acol + tt][arow] = ok ? g_Cn[ai] : 0.f;
            A2s[acol + tt][arow] = ok ? g_Sn[ai] : 0.f;
        }
        int kb = k0 + brow;
        float4 b1 = make_float4(0.f, 0.f, 0.f, 0.f), b2 = b1;
        if (kb < NT) {
            long long bi = base + (long long)kb * ND + n0 + bcol;
            b1 = *(const float4*)&g_U[bi];
            b2 = *(const float4*)&g_V[bi];
        }
        *(float4*)&B1s[brow][bcol] = b1;
        *(float4*)&B2s[brow][bcol] = b2;
        __syncthreads();
#pragma unroll
        for (int k = 0; k < 16; k++) {
            float4 a1 = *(const float4*)&A1s[k][ty << 2];
            float4 a2 = *(const float4*)&A2s[k][ty << 2];
            float4 v1 = *(const float4*)&B1s[k][tx << 2];
            float4 v2 = *(const float4*)&B2s[k][tx << 2];
            float p[4] = {a1.x, a1.y, a1.z, a1.w};
            float q[4] = {a2.x, a2.y, a2.z, a2.w};
            float r[4] = {v1.x, v1.y, v1.z, v1.w};
            float s[4] = {v2.x, v2.y, v2.z, v2.w};
#pragma unroll
            for (int i = 0; i < 4; i++)
#pragma unroll
                for (int j = 0; j < 4; j++) {
                    acc[i][j] = fmaf(p[i], r[j], acc[i][j]);
                    acc[i][j] = fmaf(-q[i], s[j], acc[i][j]);
                }
        }
        __syncthreads();
    }
#pragma unroll
    for (int i = 0; i < 4; i++) {
        int mm = m0 + (ty << 2) + i;
        if (mm < NT) {
#pragma unroll
            for (int j = 0; j < 4; j++) {
                long long ci = base + (long long)mm * ND + n0 + (tx << 2) + j;
                g_t[ci] += acc[i][j];
            }
        }
    }
}

// ---------------- generic tiled SGEMM (exact tiles: M%64==0, N%64==0, K%16==0) ----------------
// BETA: accumulate into C; BIAS: add bias[n]; ACT: leaky relu(0.01)
template<int BETA, int BIAS, int ACT>
__global__ void sgemm_kernel(const float* __restrict__ A, const float* __restrict__ B,
                             float* __restrict__ C, const float* __restrict__ bias,
                             int M, int N, int K) {
    __shared__ float As[16][68], Bs[16][68];
    int tid = threadIdx.x;
    int tx = tid & 15, ty = tid >> 4;
    int m0 = blockIdx.y << 6, n0 = blockIdx.x << 6;
    int arow = tid >> 2, acol = (tid & 3) << 2;
    int brow = tid >> 4, bcol = (tid & 15) << 2;
    float acc[4][4] = {};
    const float* Ap = A + (long long)(m0 + arow) * K + acol;
    const float* Bp = B + (long long)brow * N + n0 + bcol;
    for (int k0 = 0; k0 < K; k0 += 16) {
        float4 av = *(const float4*)(Ap + k0);
        As[acol + 0][arow] = av.x; As[acol + 1][arow] = av.y;
        As[acol + 2][arow] = av.z; As[acol + 3][arow] = av.w;
        *(float4*)&Bs[brow][bcol] = *(const float4*)(Bp + (long long)k0 * N);
        __syncthreads();
#pragma unroll
        for (int k = 0; k < 16; k++) {
            float4 a = *(const float4*)&As[k][ty << 2];
            float4 b = *(const float4*)&Bs[k][tx << 2];
            float ar[4] = {a.x, a.y, a.z, a.w};
            float br[4] = {b.x, b.y, b.z, b.w};
#pragma unroll
            for (int i = 0; i < 4; i++)
#pragma unroll
                for (int j = 0; j < 4; j++)
                    acc[i][j] = fmaf(ar[i], br[j], acc[i][j]);
        }
        __syncthreads();
    }
#pragma unroll
    for (int i = 0; i < 4; i++) {
        long long row = m0 + (ty << 2) + i;
#pragma unroll
        for (int j = 0; j < 4; j++) {
            int n = n0 + (tx << 2) + j;
            float v = acc[i][j];
            if (BIAS) v += bias[n];
            if (ACT)  v = v > 0.f ? v : 0.01f * v;
            float* cp = &C[row * N + n];
            if (BETA) v += *cp;
            *cp = v;
        }
    }
}

// ---------------- mean pool over tokens ----------------
__global__ void pool_kernel() {
    int b = blockIdx.x, d = threadIdx.x;
    const float* p = g_t + (long long)b * NT * ND + d;
    float s = 0.f;
#pragma unroll 8
    for (int n = 0; n < NT; n++) s += p[(long long)n * ND];
    g_pooled[b * ND + d] = s * (1.f / 1025.f);
}

// ---------------- head: LN(pooled) @ head_w + head_b -> softmax ----------------
__global__ void head_kernel(const float* __restrict__ hw, const float* __restrict__ hb,
                            const float* __restrict__ gs, const float* __restrict__ gb,
                            float* __restrict__ out) {
    __shared__ float sbuf[32];
    __shared__ float lnp[256];
    int b = blockIdx.x, tid = threadIdx.x;
    float v = g_pooled[b * ND + tid];
    float mean = block_sum(v, sbuf) * (1.f / 256.f);
    float d = v - mean;
    float var = block_sum(d * d, sbuf) * (1.f / 256.f);
    lnp[tid] = d * rsqrtf(var + 1e-5f) * gs[tid] + gb[tid];
    __syncthreads();
    float lg[4];
#pragma unroll
    for (int j = 0; j < 4; j++) {
        int n = tid + j * 256;
        float s = -3.4e38f;
        if (n < NCLS) {
            s = hb[n];
            for (int k = 0; k < ND; k++) s = fmaf(lnp[k], hw[k * NCLS + n], s);
        }
        lg[j] = s;
    }
    float lmax = fmaxf(fmaxf(lg[0], lg[1]), fmaxf(lg[2], lg[3]));
    float mx = block_max(lmax, sbuf);
    float es = 0.f;
#pragma unroll
    for (int j = 0; j < 4; j++) {
        int n = tid + j * 256;
        if (n < NCLS) { lg[j] = expf(lg[j] - mx); es += lg[j]; }
    }
    float tot = block_sum(es, sbuf);
    float inv = 1.f / tot;
#pragma unroll
    for (int j = 0; j < 4; j++) {
        int n = tid + j * 256;
        if (n < NCLS) out[(long long)b * NCLS + n] = lg[j] * inv;
    }
}

// ---------------- host launch ----------------
extern "C" void kernel_launch(void* const* d_in, const int* in_sizes, int n_in,
                              void* d_out, int out_size) {
    const float* x      = (const float*)d_in[0];
    const float* conv_w = (const float*)d_in[1];
    const float* conv_b = (const float*)d_in[2];
    const float* pos    = (const float*)d_in[3];
    const float* cls    = (const float*)d_in[4];
    const float* ln1_s  = (const float*)d_in[5];
    const float* ln1_b  = (const float*)d_in[6];
    const float* ln2_s  = (const float*)d_in[7];
    const float* ln2_b  = (const float*)d_in[8];
    const float* w1     = (const float*)d_in[9];
    const float* b1     = (const float*)d_in[10];
    const float* w2     = (const float*)d_in[11];
    const float* b2     = (const float*)d_in[12];
    const float* hls    = (const float*)d_in[13];
    const float* hlb    = (const float*)d_in[14];
    const float* hw     = (const float*)d_in[15];
    const float* hb     = (const float*)d_in[16];
    float* out = (float*)d_out;

    float *t, *h, *hid;
    cudaGetSymbolAddress((void**)&t,   g_t);
    cudaGetSymbolAddress((void**)&h,   g_h);
    cudaGetSymbolAddress((void**)&hid, g_hid);

    fill_dft_d<<<256, 256>>>();
    fill_dft_n<<<NT, 256>>>();
    transpose_w<<<768, 256>>>(conv_w);
    patch_embed<<<dim3(128, 64), 256>>>(x);
    assemble<<<dim3(NT, 64), 256>>>(conv_b, pos, cls);

    const int MROWS = 64 * NT;  // 65600 = 64*1025, divisible by 64
    for (int i = 0; i < 6; i++) {
        ln_kernel<<<MROWS, 256>>>(t, h, ln1_s + (size_t)i * ND, ln1_b + (size_t)i * ND);
        dft_gemm<<<dim3(4, 1025), 256>>>();
        mix_gemm<<<dim3(4, 17, 64), 256>>>();
        ln_kernel<<<MROWS, 256>>>(t, h, ln2_s + (size_t)i * ND, ln2_b + (size_t)i * ND);
        sgemm_kernel<0, 1, 1><<<dim3(16, 1025), 256>>>(
            h, w1 + (size_t)i * ND * NH, hid, b1 + (size_t)i * NH, MROWS, NH, ND);
        sgemm_kernel<1, 1, 0><<<dim3(4, 1025), 256>>>(
            hid, w2 + (size_t)i * NH * ND, t, b2 + (size_t)i * ND, MROWS, ND, NH);
    }

    pool_kernel<<<64, 256>>>();
    head_kernel<<<64, 256>>>(hw, hb, hls, hlb, out);
}

// round 8
// speedup vs baseline: 2.3078x; 2.3078x over previous
#include <cuda_runtime.h>
#include <cuda_bf16.h>
#include <cstdint>

#define NTP   1152
#define NTOK  1025
#define ND    256
#define NH    1024
#define NCLS  1000
#define NB    64
#define MROWS (NB*NTP)
#define KMIX  2304
#define KPE   768
#define MPE   (NB*1024)
#define L     6

// ---------------- static scratch ----------------
__device__ float          g_t    [(long long)MROWS*ND];
__device__ float          g_pooled[NB*ND];
__device__ __nv_bfloat16  g_hhi  [(long long)MROWS*ND];
__device__ __nv_bfloat16  g_hlo  [(long long)MROWS*ND];
__device__ __nv_bfloat16  g_Phi  [(long long)NB*ND*KMIX];
__device__ __nv_bfloat16  g_Plo  [(long long)NB*ND*KMIX];
__device__ __nv_bfloat16  g_hidhi[(long long)MROWS*NH];
__device__ __nv_bfloat16  g_hidlo[(long long)MROWS*NH];
__device__ __nv_bfloat16  g_Cnhi [(long long)NTP*KMIX];
__device__ __nv_bfloat16  g_Cnlo [(long long)NTP*KMIX];
__device__ __nv_bfloat16  g_Bdhi [512*ND];
__device__ __nv_bfloat16  g_Bdlo [512*ND];
__device__ __nv_bfloat16  g_w1thi[(long long)L*NH*ND];
__device__ __nv_bfloat16  g_w1tlo[(long long)L*NH*ND];
__device__ __nv_bfloat16  g_w2thi[(long long)L*ND*NH];
__device__ __nv_bfloat16  g_w2tlo[(long long)L*ND*NH];
__device__ __nv_bfloat16  g_wphi [ND*KPE];
__device__ __nv_bfloat16  g_wplo [ND*KPE];
__device__ __nv_bfloat16  g_pahi [(long long)MPE*KPE];
__device__ __nv_bfloat16  g_palo [(long long)MPE*KPE];

// ---------------- helpers ----------------
__device__ __forceinline__ uint32_t smem_to_u32(const void* p) {
    uint32_t a;
    asm("{ .reg .u64 t; cvta.to.shared.u64 t, %1; cvt.u32.u64 %0, t; }" : "=r"(a) : "l"(p));
    return a;
}
__device__ __forceinline__ void split2(float v, __nv_bfloat16* hi, __nv_bfloat16* lo) {
    __nv_bfloat16 h = __float2bfloat16(v);
    *hi = h;
    *lo = __float2bfloat16(v - __bfloat162float(h));
}

#define LDSM4(r, addr) \
    asm volatile("ldmatrix.sync.aligned.m8n8.x4.shared.b16 {%0,%1,%2,%3}, [%4];" \
                 : "=r"((r)[0]), "=r"((r)[1]), "=r"((r)[2]), "=r"((r)[3]) : "r"(addr))

#define MMA(d, a, b) \
    asm volatile("mma.sync.aligned.m16n8k16.row.col.f32.bf16.bf16.f32 " \
                 "{%0,%1,%2,%3},{%4,%5,%6,%7},{%8,%9},{%0,%1,%2,%3};" \
                 : "+f"((d)[0]), "+f"((d)[1]), "+f"((d)[2]), "+f"((d)[3]) \
                 : "r"((a)[0]), "r"((a)[1]), "r"((a)[2]), "r"((a)[3]), "r"((b)[0]), "r"((b)[1]))

#define CP16(dst, src) \
    asm volatile("cp.async.cg.shared.global [%0], [%1], 16;" :: "r"(dst), "l"(src))
#define CP_COMMIT() asm volatile("cp.async.commit_group;" ::: "memory")
#define CP_WAIT0()  asm volatile("cp.async.wait_group 0;" ::: "memory")
#define CP_WAIT1()  asm volatile("cp.async.wait_group 1;" ::: "memory")

// ---------------- GEMM engine ----------------
// BM=128, BN=128, BK=64; 256 threads, 8 warps (4m x 2n), warp tile 32x64.
// A: [M][K] bf16 hi/lo; B: [N][K] bf16 hi/lo (K contiguous). D = A*B^T (fp32).
// MODE 0: A=[Cd;Sd](512xK256) B=h[b] -> P split (sign for Sd half)
// MODE 1: A=[Cn|Sn](1152x2304) B=P[b] -> t +=
// MODE 2: A=h B=w1t[li] K=256  -> leaky(D+b1) -> hid split
// MODE 3: A=hid B=w2t[li] K=1024 -> t += D + b2
// MODE 4: A=pa B=wp K=768 -> t = D + conv_b + pos
#define STR 72
#define TILE_H (128*STR)
#define STAGE_H (4*TILE_H)
#define DSMB (2*STAGE_H*2)

template<int MODE> struct CF {
    static constexpr int K   = (MODE == 1) ? KMIX : (MODE == 3) ? NH : (MODE == 4) ? KPE : ND;
    static constexpr int NCH = K / 64;
};

__device__ __forceinline__ void load4(uint32_t sbase, const __nv_bfloat16* __restrict__ g,
                                      int K, int k0, int tid) {
#pragma unroll
    for (int i = 0; i < 4; i++) {
        int idx = tid + (i << 8);
        int row = idx >> 3, c8 = (idx & 7) << 3;
        uint32_t d = sbase + (uint32_t)((row * STR + c8) << 1);
        const __nv_bfloat16* gp = g + (long long)row * K + k0 + c8;
        CP16(d, gp);
    }
}

template<int MODE>
__global__ void __launch_bounds__(256, 1)
gemm_mma(const float* __restrict__ x0, const float* __restrict__ x1, int li) {
    constexpr int K = CF<MODE>::K, NCH = CF<MODE>::NCH;
    extern __shared__ char dsm[];
    uint32_t sb = smem_to_u32(dsm);
    int tid = threadIdx.x, wid = tid >> 5, lid = tid & 31;
    int wm = wid & 3, wn = wid >> 2;
    int n0 = blockIdx.y << 7, z = blockIdx.z;
    long long aRow0 = (long long)blockIdx.x << 7;

    const __nv_bfloat16 *Ahi, *Alo, *Bhi, *Blo;
    if      (MODE == 0) { Ahi = g_Bdhi + aRow0 * K;  Alo = g_Bdlo + aRow0 * K;
                          long long r = (long long)z * NTP + n0;
                          Bhi = g_hhi + r * K;       Blo = g_hlo + r * K; }
    else if (MODE == 1) { Ahi = g_Cnhi + aRow0 * K;  Alo = g_Cnlo + aRow0 * K;
                          long long r = (long long)z * ND + n0;
                          Bhi = g_Phi + r * K;       Blo = g_Plo + r * K; }
    else if (MODE == 2) { Ahi = g_hhi + aRow0 * K;   Alo = g_hlo + aRow0 * K;
                          long long r = (long long)li * NH + n0;
                          Bhi = g_w1thi + r * K;     Blo = g_w1tlo + r * K; }
    else if (MODE == 3) { Ahi = g_hidhi + aRow0 * K; Alo = g_hidlo + aRow0 * K;
                          long long r = (long long)li * ND + n0;
                          Bhi = g_w2thi + r * K;     Blo = g_w2tlo + r * K; }
    else                { Ahi = g_pahi + aRow0 * K;  Alo = g_palo + aRow0 * K;
                          Bhi = g_wphi + (long long)n0 * K;
                          Blo = g_wplo + (long long)n0 * K; }

    float acc[2][8][4];
#pragma unroll
    for (int i = 0; i < 2; i++)
#pragma unroll
        for (int j = 0; j < 8; j++)
#pragma unroll
            for (int q = 0; q < 4; q++) acc[i][j][q] = 0.f;

    // lane addressing for ldmatrix
    int a_r = lid & 15, a_c = (lid >> 4) << 3;
    int b_grp = lid >> 3, b_w = lid & 7;
    int b_roff = ((b_grp >> 1) << 3) + b_w, b_coff = (b_grp & 1) << 3;

    // prefetch chunk 0
    {
        uint32_t s0 = sb;
        load4(s0 + 0 * TILE_H * 2, Ahi, K, 0, tid);
        load4(s0 + 1 * TILE_H * 2, Alo, K, 0, tid);
        load4(s0 + 2 * TILE_H * 2, Bhi, K, 0, tid);
        load4(s0 + 3 * TILE_H * 2, Blo, K, 0, tid);
        CP_COMMIT();
    }

    for (int c = 0; c < NCH; c++) {
        if (c + 1 < NCH) {
            uint32_t s1 = sb + ((c + 1) & 1) * STAGE_H * 2;
            int k0 = (c + 1) << 6;
            load4(s1 + 0 * TILE_H * 2, Ahi, K, k0, tid);
            load4(s1 + 1 * TILE_H * 2, Alo, K, k0, tid);
            load4(s1 + 2 * TILE_H * 2, Bhi, K, k0, tid);
            load4(s1 + 3 * TILE_H * 2, Blo, K, k0, tid);
            CP_COMMIT();
            CP_WAIT1();
        } else {
            CP_WAIT0();
        }
        __syncthreads();
        uint32_t sc = sb + (c & 1) * STAGE_H * 2;
#pragma unroll
        for (int ks = 0; ks < 4; ks++) {
            uint32_t ah[2][4], al[2][4], bh[8][2], bl[8][2];
#pragma unroll
            for (int mi = 0; mi < 2; mi++) {
                uint32_t off = (uint32_t)(((wm * 32 + mi * 16 + a_r) * STR + ks * 16 + a_c) << 1);
                LDSM4(ah[mi], sc + 0 * TILE_H * 2 + off);
                LDSM4(al[mi], sc + 1 * TILE_H * 2 + off);
            }
#pragma unroll
            for (int nj = 0; nj < 4; nj++) {
                uint32_t off = (uint32_t)(((wn * 64 + nj * 16 + b_roff) * STR + ks * 16 + b_coff) << 1);
                uint32_t r4[4];
                LDSM4(r4, sc + 2 * TILE_H * 2 + off);
                bh[nj * 2][0] = r4[0]; bh[nj * 2][1] = r4[1];
                bh[nj * 2 + 1][0] = r4[2]; bh[nj * 2 + 1][1] = r4[3];
                LDSM4(r4, sc + 3 * TILE_H * 2 + off);
                bl[nj * 2][0] = r4[0]; bl[nj * 2][1] = r4[1];
                bl[nj * 2 + 1][0] = r4[2]; bl[nj * 2 + 1][1] = r4[3];
            }
#pragma unroll
            for (int mi = 0; mi < 2; mi++)
#pragma unroll
                for (int ni = 0; ni < 8; ni++) {
                    MMA(acc[mi][ni], ah[mi], bh[ni]);
                    MMA(acc[mi][ni], ah[mi], bl[ni]);
                    MMA(acc[mi][ni], al[mi], bh[ni]);
                }
        }
        __syncthreads();
    }

    // ---------------- epilogue ----------------
    int r_in = lid >> 2, c_in = (lid & 3) << 1;

    if (MODE == 0) {
        float sg = (aRow0 < 256) ? 1.f : -1.f;
        long long koff = (aRow0 < 256) ? 0 : NTP;
#pragma unroll
        for (int mi = 0; mi < 2; mi++)
#pragma unroll
            for (int ni = 0; ni < 8; ni++) {
                int mg = (int)aRow0 + wm * 32 + mi * 16 + r_in;
                int tok = n0 + wn * 64 + ni * 8 + c_in;
#pragma unroll
                for (int hrow = 0; hrow < 2; hrow++) {
                    int dim = (mg + hrow * 8) & 255;
                    long long off = ((long long)z * ND + dim) * KMIX + koff + tok;
                    float v0 = sg * acc[mi][ni][hrow * 2];
                    float v1 = sg * acc[mi][ni][hrow * 2 + 1];
                    __nv_bfloat16 h0, l0, h1, l1;
                    split2(v0, &h0, &l0); split2(v1, &h1, &l1);
                    __nv_bfloat162 ph; ph.x = h0; ph.y = h1;
                    __nv_bfloat162 pl; pl.x = l0; pl.y = l1;
                    *(__nv_bfloat162*)&g_Phi[off] = ph;
                    *(__nv_bfloat162*)&g_Plo[off] = pl;
                }
            }
    } else if (MODE == 1 || MODE == 3) {
#pragma unroll
        for (int mi = 0; mi < 2; mi++)
#pragma unroll
            for (int ni = 0; ni < 8; ni++) {
                long long mrow = aRow0 + wm * 32 + mi * 16 + r_in;
                if (MODE == 1) mrow += (long long)z * NTP;
                int col = n0 + wn * 64 + ni * 8 + c_in;
#pragma unroll
                for (int hrow = 0; hrow < 2; hrow++) {
                    float* tp = g_t + (mrow + hrow * 8) * ND + col;
                    float2 t2 = *(float2*)tp;
                    t2.x += acc[mi][ni][hrow * 2];
                    t2.y += acc[mi][ni][hrow * 2 + 1];
                    if (MODE == 3) { t2.x += x0[col]; t2.y += x0[col + 1]; }
                    *(float2*)tp = t2;
                }
            }
    } else if (MODE == 2) {
#pragma unroll
        for (int mi = 0; mi < 2; mi++)
#pragma unroll
            for (int ni = 0; ni < 8; ni++) {
                long long mrow = aRow0 + wm * 32 + mi * 16 + r_in;
                int col = n0 + wn * 64 + ni * 8 + c_in;
                float bb0 = x0[col], bb1 = x0[col + 1];
#pragma unroll
                for (int hrow = 0; hrow < 2; hrow++) {
                    float v0 = acc[mi][ni][hrow * 2] + bb0;
                    float v1 = acc[mi][ni][hrow * 2 + 1] + bb1;
                    v0 = v0 > 0.f ? v0 : 0.01f * v0;
                    v1 = v1 > 0.f ? v1 : 0.01f * v1;
                    __nv_bfloat16 h0, l0, h1, l1;
                    split2(v0, &h0, &l0); split2(v1, &h1, &l1);
                    __nv_bfloat162 ph; ph.x = h0; ph.y = h1;
                    __nv_bfloat162 pl; pl.x = l0; pl.y = l1;
                    long long o = (mrow + hrow * 8) * NH + col;
                    *(__nv_bfloat162*)&g_hidhi[o] = ph;
                    *(__nv_bfloat162*)&g_hidlo[o] = pl;
                }
            }
    } else {  // MODE 4
#pragma unroll
        for (int mi = 0; mi < 2; mi++)
#pragma unroll
            for (int ni = 0; ni < 8; ni++) {
                long long m = aRow0 + wm * 32 + mi * 16 + r_in;
                int col = n0 + wn * 64 + ni * 8 + c_in;
                float cb0 = x0[col], cb1 = x0[col + 1];
#pragma unroll
                for (int hrow = 0; hrow < 2; hrow++) {
                    long long mm = m + hrow * 8;
                    long long b = mm >> 10;
                    int p = (int)(mm & 1023);
                    float* tp = g_t + (b * NTP + 1 + p) * ND + col;
                    const float* pp = x1 + (long long)(1 + p) * ND + col;
                    tp[0] = acc[mi][ni][hrow * 2]     + cb0 + pp[0];
                    tp[1] = acc[mi][ni][hrow * 2 + 1] + cb1 + pp[1];
                }
            }
    }
}

// ---------------- fills ----------------
__global__ void fill_bd() {
    int i = blockIdx.x, j = threadIdx.x;
    int r = ((i & 255) * j) & 255;
    float s, c;
    sincospif(2.0f * (float)r / 256.0f, &s, &c);
    split2(i < ND ? c : s, &g_Bdhi[i * ND + j], &g_Bdlo[i * ND + j]);
}
__global__ void fill_cn() {
    int m = blockIdx.x;
    for (int k = threadIdx.x; k < KMIX; k += 256) {
        int half = (k < NTP);
        int kk = half ? k : k - NTP;
        float v = 0.f;
        if (m < NTOK && kk < NTOK) {
            int r = (int)(((long long)m * kk) % NTOK);
            float s, c;
            sincospif(2.0f * (float)r / (float)NTOK, &s, &c);
            v = half ? c : s;
        }
        split2(v, &g_Cnhi[(long long)m * KMIX + k], &g_Cnlo[(long long)m * KMIX + k]);
    }
}
__global__ void fill_wp(const float* __restrict__ w) {
    int n = blockIdx.x;
    for (int k = threadIdx.x; k < KPE; k += 256)
        split2(w[(long long)n * KPE + k], &g_wphi[n * KPE + k], &g_wplo[n * KPE + k]);
}
__global__ void fill_w1t(const float* __restrict__ w) {   // grid (NH, L), block 256
    int n = blockIdx.x, i = blockIdx.y, k = threadIdx.x;
    long long o = ((long long)i * NH + n) * ND + k;
    split2(w[((long long)i * ND + k) * NH + n], &g_w1thi[o], &g_w1tlo[o]);
}
__global__ void fill_w2t(const float* __restrict__ w) {   // grid (ND, L), block 256
    int n = blockIdx.x, i = blockIdx.y;
    for (int k = threadIdx.x; k < NH; k += 256) {
        long long o = ((long long)i * ND + n) * NH + k;
        split2(w[((long long)i * NH + k) * ND + n], &g_w2thi[o], &g_w2tlo[o]);
    }
}
__global__ void patch_gather(const float* __restrict__ x) {
    int m = blockIdx.x;
    int b = m >> 10, p = m & 1023;
    int gh = p >> 5, gw = p & 31;
    for (int k = threadIdx.x; k < KPE; k += 256) {
        int cch = k >> 8, rem = k & 255, rr = rem >> 4, q = rem & 15;
        float v = x[(((long long)b * 3 + cch) * 512 + gh * 16 + rr) * 512 + gw * 16 + q];
        split2(v, &g_pahi[(long long)m * KPE + k], &g_palo[(long long)m * KPE + k]);
    }
}
__global__ void cls_init(const float* __restrict__ cls, const float* __restrict__ pos) {
    g_t[(long long)blockIdx.x * NTP * ND + threadIdx.x] = cls[threadIdx.x] + pos[threadIdx.x];
}

// ---------------- LN + split ----------------
__device__ __forceinline__ float warp_sum(float v) {
#pragma unroll
    for (int o = 16; o > 0; o >>= 1) v += __shfl_xor_sync(0xffffffffu, v, o);
    return v;
}
__device__ __forceinline__ float warp_max(float v) {
#pragma unroll
    for (int o = 16; o > 0; o >>= 1) v = fmaxf(v, __shfl_xor_sync(0xffffffffu, v, o));
    return v;
}
__global__ void ln_split(const float* __restrict__ gam, const float* __restrict__ bet) {
    int tid = threadIdx.x, wid = tid >> 5, lane = tid & 31;
    long long row = (long long)blockIdx.x * 8 + wid;
    long long o = row * ND + lane * 8;
    if ((int)(row % NTP) >= NTOK) {
        uint4 zz = make_uint4(0, 0, 0, 0);
        *(uint4*)(g_hhi + o) = zz;
        *(uint4*)(g_hlo + o) = zz;
        return;
    }
    float v[8];
    float4 a = *(const float4*)(g_t + o), b = *(const float4*)(g_t + o + 4);
    v[0]=a.x; v[1]=a.y; v[2]=a.z; v[3]=a.w; v[4]=b.x; v[5]=b.y; v[6]=b.z; v[7]=b.w;
    float s = 0.f;
#pragma unroll
    for (int k = 0; k < 8; k++) s += v[k];
    float mean = warp_sum(s) * (1.f / 256.f);
    float q = 0.f;
#pragma unroll
    for (int k = 0; k < 8; k++) { float d = v[k] - mean; q += d * d; }
    float rstd = rsqrtf(warp_sum(q) * (1.f / 256.f) + 1e-5f);
    float4 g0 = *(const float4*)(gam + lane * 8), g1 = *(const float4*)(gam + lane * 8 + 4);
    float4 b0 = *(const float4*)(bet + lane * 8), b1 = *(const float4*)(bet + lane * 8 + 4);
    float gg[8] = {g0.x,g0.y,g0.z,g0.w,g1.x,g1.y,g1.z,g1.w};
    float bb[8] = {b0.x,b0.y,b0.z,b0.w,b1.x,b1.y,b1.z,b1.w};
#pragma unroll
    for (int k = 0; k < 8; k++)
        split2((v[k] - mean) * rstd * gg[k] + bb[k], &g_hhi[o + k], &g_hlo[o + k]);
}

// ---------------- pool + head ----------------
__global__ void pool_kernel() {
    int b = blockIdx.x, d = threadIdx.x;
    const float* p = g_t + (long long)b * NTP * ND + d;
    float s = 0.f;
#pragma unroll 8
    for (int n = 0; n < NTOK; n++) s += p[(long long)n * ND];
    g_pooled[b * ND + d] = s * (1.f / 1025.f);
}
__device__ float block_sum(float v, float* sbuf) {
    int tid = threadIdx.x;
    float w = warp_sum(v);
    if ((tid & 31) == 0) sbuf[tid >> 5] = w;
    __syncthreads();
    float r = (tid < 8) ? sbuf[tid] : 0.f;
    if (tid < 32) { r = warp_sum(r); if (tid == 0) sbuf[0] = r; }
    __syncthreads();
    float res = sbuf[0];
    __syncthreads();
    return res;
}
__device__ float block_max(float v, float* sbuf) {
    int tid = threadIdx.x;
    float w = warp_max(v);
    if ((tid & 31) == 0) sbuf[tid >> 5] = w;
    __syncthreads();
    float r = (tid < 8) ? sbuf[tid] : -3.4e38f;
    if (tid < 32) { r = warp_max(r); if (tid == 0) sbuf[0] = r; }
    __syncthreads();
    float res = sbuf[0];
    __syncthreads();
    return res;
}
__global__ void head_kernel(const float* __restrict__ hw, const float* __restrict__ hb,
                            const float* __restrict__ gs, const float* __restrict__ gb,
                            float* __restrict__ out) {
    __shared__ float sbuf[32];
    __shared__ float lnp[256];
    int b = blockIdx.x, tid = threadIdx.x;
    float v = g_pooled[b * ND + tid];
    float mean = block_sum(v, sbuf) * (1.f / 256.f);
    float d = v - mean;
    float var = block_sum(d * d, sbuf) * (1.f / 256.f);
    lnp[tid] = d * rsqrtf(var + 1e-5f) * gs[tid] + gb[tid];
    __syncthreads();
    float lg[4];
#pragma unroll
    for (int j = 0; j < 4; j++) {
        int n = tid + j * 256;
        float s = -3.4e38f;
        if (n < NCLS) {
            s = hb[n];
            for (int k = 0; k < ND; k++) s = fmaf(lnp[k], hw[k * NCLS + n], s);
        }
        lg[j] = s;
    }
    float mx = block_max(fmaxf(fmaxf(lg[0], lg[1]), fmaxf(lg[2], lg[3])), sbuf);
    float es = 0.f;
#pragma unroll
    for (int j = 0; j < 4; j++) {
        int n = tid + j * 256;
        if (n < NCLS) { lg[j] = expf(lg[j] - mx); es += lg[j]; }
    }
    float inv = 1.f / block_sum(es, sbuf);
#pragma unroll
    for (int j = 0; j < 4; j++) {
        int n = tid + j * 256;
        if (n < NCLS) out[(long long)b * NCLS + n] = lg[j] * inv;
    }
}

// ---------------- host ----------------
extern "C" void kernel_launch(void* const* d_in, const int* in_sizes, int n_in,
                              void* d_out, int out_size) {
    const float* x      = (const float*)d_in[0];
    const float* conv_w = (const float*)d_in[1];
    const float* conv_b = (const float*)d_in[2];
    const float* pos    = (const float*)d_in[3];
    const float* cls    = (const float*)d_in[4];
    const float* ln1_s  = (const float*)d_in[5];
    const float* ln1_b  = (const float*)d_in[6];
    const float* ln2_s  = (const float*)d_in[7];
    const float* ln2_b  = (const float*)d_in[8];
    const float* w1     = (const float*)d_in[9];
    const float* b1     = (const float*)d_in[10];
    const float* w2     = (const float*)d_in[11];
    const float* b2     = (const float*)d_in[12];
    const float* hls    = (const float*)d_in[13];
    const float* hlb    = (const float*)d_in[14];
    const float* hw     = (const float*)d_in[15];
    const float* hb     = (const float*)d_in[16];
    float* out = (float*)d_out;

    cudaFuncSetAttribute(gemm_mma<0>, cudaFuncAttributeMaxDynamicSharedMemorySize, DSMB);
    cudaFuncSetAttribute(gemm_mma<1>, cudaFuncAttributeMaxDynamicSharedMemorySize, DSMB);
    cudaFuncSetAttribute(gemm_mma<2>, cudaFuncAttributeMaxDynamicSharedMemorySize, DSMB);
    cudaFuncSetAttribute(gemm_mma<3>, cudaFuncAttributeMaxDynamicSharedMemorySize, DSMB);
    cudaFuncSetAttribute(gemm_mma<4>, cudaFuncAttributeMaxDynamicSharedMemorySize, DSMB);

    fill_bd<<<512, 256>>>();
    fill_cn<<<NTP, 256>>>();
    fill_wp<<<256, 256>>>(conv_w);
    fill_w1t<<<dim3(NH, L), 256>>>(w1);
    fill_w2t<<<dim3(ND, L), 256>>>(w2);
    patch_gather<<<MPE, 256>>>(x);
    cls_init<<<NB, 256>>>(cls, pos);
    gemm_mma<4><<<dim3(MPE / 128, ND / 128, 1), 256, DSMB>>>(conv_b, pos, 0);

    for (int i = 0; i < 6; i++) {
        ln_split<<<MROWS / 8, 256>>>(ln1_s + (size_t)i * ND, ln1_b + (size_t)i * ND);
        gemm_mma<0><<<dim3(4, NTP / 128, NB), 256, DSMB>>>(nullptr, nullptr, i);
        gemm_mma<1><<<dim3(NTP / 128, ND / 128, NB), 256, DSMB>>>(nullptr, nullptr, i);
        ln_split<<<MROWS / 8, 256>>>(ln2_s + (size_t)i * ND, ln2_b + (size_t)i * ND);
        gemm_mma<2><<<dim3(MROWS / 128, NH / 128, 1), 256, DSMB>>>(b1 + (size_t)i * NH, nullptr, i);
        gemm_mma<3><<<dim3(MROWS / 128, ND / 128, 1), 256, DSMB>>>(b2 + (size_t)i * ND, nullptr, i);
    }

    pool_kernel<<<NB, 256>>>();
    head_kernel<<<NB, 256>>>(hw, hb, hls, hlb, out);
}

// round 9
// speedup vs baseline: 2.9486x; 1.2777x over previous
#include <cuda_runtime.h>
#include <cuda_bf16.h>
#include <cstdint>

#define NTP   1152
#define NTOK  1025
#define ND    256
#define NH    1024
#define NCLS  1000
#define NB    64
#define MROWS (NB*NTP)
#define KMIX  2304
#define KPE   768
#define MPE   (NB*1024)
#define L     6

// ---------------- static scratch ----------------
__device__ float          g_t    [(long long)MROWS*ND];
__device__ float          g_pooled[NB*ND];
__device__ __nv_bfloat16  g_hhi  [(long long)MROWS*ND];
__device__ __nv_bfloat16  g_hlo  [(long long)MROWS*ND];
__device__ __nv_bfloat16  g_Phi  [(long long)NB*ND*KMIX];
__device__ __nv_bfloat16  g_Plo  [(long long)NB*ND*KMIX];
__device__ __nv_bfloat16  g_hidhi[(long long)MROWS*NH];
__device__ __nv_bfloat16  g_Cnhi [(long long)NTP*KMIX];
__device__ __nv_bfloat16  g_Cnlo [(long long)NTP*KMIX];
__device__ __nv_bfloat16  g_Bdhi [512*ND];
__device__ __nv_bfloat16  g_Bdlo [512*ND];
__device__ __nv_bfloat16  g_w1thi[(long long)L*NH*ND];
__device__ __nv_bfloat16  g_w2thi[(long long)L*ND*NH];
__device__ __nv_bfloat16  g_wphi [ND*KPE];
__device__ __nv_bfloat16  g_wplo [ND*KPE];
__device__ __nv_bfloat16  g_pahi [(long long)MPE*KPE];
__device__ __nv_bfloat16  g_palo [(long long)MPE*KPE];

// ---------------- helpers ----------------
__device__ __forceinline__ uint32_t smem_to_u32(const void* p) {
    uint32_t a;
    asm("{ .reg .u64 t; cvta.to.shared.u64 t, %1; cvt.u32.u64 %0, t; }" : "=r"(a) : "l"(p));
    return a;
}
__device__ __forceinline__ void split2(float v, __nv_bfloat16* hi, __nv_bfloat16* lo) {
    __nv_bfloat16 h = __float2bfloat16(v);
    *hi = h;
    *lo = __float2bfloat16(v - __bfloat162float(h));
}

#define LDSM4(r, addr) \
    asm volatile("ldmatrix.sync.aligned.m8n8.x4.shared.b16 {%0,%1,%2,%3}, [%4];" \
                 : "=r"((r)[0]), "=r"((r)[1]), "=r"((r)[2]), "=r"((r)[3]) : "r"(addr))

#define MMA(d, a, b) \
    asm volatile("mma.sync.aligned.m16n8k16.row.col.f32.bf16.bf16.f32 " \
                 "{%0,%1,%2,%3},{%4,%5,%6,%7},{%8,%9},{%0,%1,%2,%3};" \
                 : "+f"((d)[0]), "+f"((d)[1]), "+f"((d)[2]), "+f"((d)[3]) \
                 : "r"((a)[0]), "r"((a)[1]), "r"((a)[2]), "r"((a)[3]), "r"((b)[0]), "r"((b)[1]))

#define CP16(dst, src) \
    asm volatile("cp.async.cg.shared.global [%0], [%1], 16;" :: "r"(dst), "l"(src))
#define CP_COMMIT() asm volatile("cp.async.commit_group;" ::: "memory")
#define CP_WAIT0()  asm volatile("cp.async.wait_group 0;" ::: "memory")
#define CP_WAIT1()  asm volatile("cp.async.wait_group 1;" ::: "memory")

// ---------------- GEMM engine ----------------
// BM=128, BN=128, BK=64; 256 threads, 8 warps (4m x 2n), warp tile 32x64.
// A: [M][K] bf16; B: [N][K] bf16 (K contiguous). D = A*B^T (fp32 accum).
// SPLIT=1: hi/lo operands, 3 MMAs per product (hh+hl+lh).
// MODE 0: A=[Cd;Sd](512xK256) B=h[b] -> P split (sign for Sd half)   [SPLIT]
// MODE 1: A=[Cn|Sn](1152x2304) B=P[b] -> t +=                        [SPLIT]
// MODE 2: A=h(hi) B=w1t[li] K=256  -> leaky(D+b1) -> hidhi           [plain]
// MODE 3: A=hidhi B=w2t[li] K=1024 -> t += D + b2                    [plain]
// MODE 4: A=pa B=wp K=768 -> t = D + conv_b + pos                    [SPLIT]
#define STR 72
#define TILE_H (128*STR)

template<int MODE> struct CF {
    static constexpr int K     = (MODE == 1) ? KMIX : (MODE == 3) ? NH : (MODE == 4) ? KPE : ND;
    static constexpr int NCH   = K / 64;
    static constexpr int SPLIT = (MODE == 2 || MODE == 3) ? 0 : 1;
    static constexpr int NTIL  = SPLIT ? 4 : 2;                 // tiles per stage
    static constexpr int STB   = NTIL * TILE_H * 2;             // stage bytes
    static constexpr int DSMB  = 2 * STB;
};

__device__ __forceinline__ void load4(uint32_t sbase, const __nv_bfloat16* __restrict__ g,
                                      int K, int k0, int tid) {
#pragma unroll
    for (int i = 0; i < 4; i++) {
        int idx = tid + (i << 8);
        int row = idx >> 3, c8 = (idx & 7) << 3;
        uint32_t d = sbase + (uint32_t)((row * STR + c8) << 1);
        const __nv_bfloat16* gp = g + (long long)row * K + k0 + c8;
        CP16(d, gp);
    }
}

template<int MODE>
__global__ void __launch_bounds__(256, 1)
gemm_mma(const float* __restrict__ x0, const float* __restrict__ x1, int li) {
    constexpr int K = CF<MODE>::K, NCH = CF<MODE>::NCH;
    constexpr int SPLIT = CF<MODE>::SPLIT;
    constexpr int STB = CF<MODE>::STB;
    constexpr uint32_t OF_AH = 0;
    constexpr uint32_t OF_AL = TILE_H * 2;                       // only if SPLIT
    constexpr uint32_t OF_BH = (SPLIT ? 2 : 1) * TILE_H * 2;
    constexpr uint32_t OF_BL = 3 * TILE_H * 2;                   // only if SPLIT

    extern __shared__ char dsm[];
    uint32_t sb = smem_to_u32(dsm);
    int tid = threadIdx.x, wid = tid >> 5, lid = tid & 31;
    int wm = wid & 3, wn = wid >> 2;
    int n0 = blockIdx.y << 7, z = blockIdx.z;
    long long aRow0 = (long long)blockIdx.x << 7;

    const __nv_bfloat16 *Ahi, *Alo = nullptr, *Bhi, *Blo = nullptr;
    if      (MODE == 0) { Ahi = g_Bdhi + aRow0 * K;  Alo = g_Bdlo + aRow0 * K;
                          long long r = (long long)z * NTP + n0;
                          Bhi = g_hhi + r * K;       Blo = g_hlo + r * K; }
    else if (MODE == 1) { Ahi = g_Cnhi + aRow0 * K;  Alo = g_Cnlo + aRow0 * K;
                          long long r = (long long)z * ND + n0;
                          Bhi = g_Phi + r * K;       Blo = g_Plo + r * K; }
    else if (MODE == 2) { Ahi = g_hhi + aRow0 * K;
                          Bhi = g_w1thi + ((long long)li * NH + n0) * K; }
    else if (MODE == 3) { Ahi = g_hidhi + aRow0 * K;
                          Bhi = g_w2thi + ((long long)li * ND + n0) * K; }
    else                { Ahi = g_pahi + aRow0 * K;  Alo = g_palo + aRow0 * K;
                          Bhi = g_wphi + (long long)n0 * K;
                          Blo = g_wplo + (long long)n0 * K; }

    float acc[2][8][4];
#pragma unroll
    for (int i = 0; i < 2; i++)
#pragma unroll
        for (int j = 0; j < 8; j++)
#pragma unroll
            for (int q = 0; q < 4; q++) acc[i][j][q] = 0.f;

    int a_r = lid & 15, a_c = (lid >> 4) << 3;
    int b_grp = lid >> 3, b_w = lid & 7;
    int b_roff = ((b_grp >> 1) << 3) + b_w, b_coff = (b_grp & 1) << 3;

    // prefetch chunk 0
    {
        load4(sb + OF_AH, Ahi, K, 0, tid);
        if (SPLIT) load4(sb + OF_AL, Alo, K, 0, tid);
        load4(sb + OF_BH, Bhi, K, 0, tid);
        if (SPLIT) load4(sb + OF_BL, Blo, K, 0, tid);
        CP_COMMIT();
    }

    for (int c = 0; c < NCH; c++) {
        if (c + 1 < NCH) {
            uint32_t s1 = sb + ((c + 1) & 1) * STB;
            int k0 = (c + 1) << 6;
            load4(s1 + OF_AH, Ahi, K, k0, tid);
            if (SPLIT) load4(s1 + OF_AL, Alo, K, k0, tid);
            load4(s1 + OF_BH, Bhi, K, k0, tid);
            if (SPLIT) load4(s1 + OF_BL, Blo, K, k0, tid);
            CP_COMMIT();
            CP_WAIT1();
        } else {
            CP_WAIT0();
        }
        __syncthreads();
        uint32_t sc = sb + (c & 1) * STB;
#pragma unroll
        for (int ks = 0; ks < 4; ks++) {
            uint32_t ah[2][4], al[2][4], bh[8][2], bl[8][2];
#pragma unroll
            for (int mi = 0; mi < 2; mi++) {
                uint32_t off = (uint32_t)(((wm * 32 + mi * 16 + a_r) * STR + ks * 16 + a_c) << 1);
                LDSM4(ah[mi], sc + OF_AH + off);
                if (SPLIT) LDSM4(al[mi], sc + OF_AL + off);
            }
#pragma unroll
            for (int nj = 0; nj < 4; nj++) {
                uint32_t off = (uint32_t)(((wn * 64 + nj * 16 + b_roff) * STR + ks * 16 + b_coff) << 1);
                uint32_t r4[4];
                LDSM4(r4, sc + OF_BH + off);
                bh[nj * 2][0] = r4[0]; bh[nj * 2][1] = r4[1];
                bh[nj * 2 + 1][0] = r4[2]; bh[nj * 2 + 1][1] = r4[3];
                if (SPLIT) {
                    LDSM4(r4, sc + OF_BL + off);
                    bl[nj * 2][0] = r4[0]; bl[nj * 2][1] = r4[1];
                    bl[nj * 2 + 1][0] = r4[2]; bl[nj * 2 + 1][1] = r4[3];
                }
            }
#pragma unroll
            for (int mi = 0; mi < 2; mi++)
#pragma unroll
                for (int ni = 0; ni < 8; ni++) {
                    MMA(acc[mi][ni], ah[mi], bh[ni]);
                    if (SPLIT) {
                        MMA(acc[mi][ni], ah[mi], bl[ni]);
                        MMA(acc[mi][ni], al[mi], bh[ni]);
                    }
                }
        }
        __syncthreads();
    }

    // ---------------- epilogue ----------------
    int r_in = lid >> 2, c_in = (lid & 3) << 1;

    if (MODE == 0) {
        float sg = (aRow0 < 256) ? 1.f : -1.f;
        long long koff = (aRow0 < 256) ? 0 : NTP;
#pragma unroll
        for (int mi = 0; mi < 2; mi++)
#pragma unroll
            for (int ni = 0; ni < 8; ni++) {
                int mg = (int)aRow0 + wm * 32 + mi * 16 + r_in;
                int tok = n0 + wn * 64 + ni * 8 + c_in;
#pragma unroll
                for (int hrow = 0; hrow < 2; hrow++) {
                    int dim = (mg + hrow * 8) & 255;
                    long long off = ((long long)z * ND + dim) * KMIX + koff + tok;
                    float v0 = sg * acc[mi][ni][hrow * 2];
                    float v1 = sg * acc[mi][ni][hrow * 2 + 1];
                    __nv_bfloat16 h0, l0, h1, l1;
                    split2(v0, &h0, &l0); split2(v1, &h1, &l1);
                    __nv_bfloat162 ph; ph.x = h0; ph.y = h1;
                    __nv_bfloat162 pl; pl.x = l0; pl.y = l1;
                    *(__nv_bfloat162*)&g_Phi[off] = ph;
                    *(__nv_bfloat162*)&g_Plo[off] = pl;
                }
            }
    } else if (MODE == 1 || MODE == 3) {
#pragma unroll
        for (int mi = 0; mi < 2; mi++)
#pragma unroll
            for (int ni = 0; ni < 8; ni++) {
                long long mrow = aRow0 + wm * 32 + mi * 16 + r_in;
                if (MODE == 1) mrow += (long long)z * NTP;
                int col = n0 + wn * 64 + ni * 8 + c_in;
#pragma unroll
                for (int hrow = 0; hrow < 2; hrow++) {
                    float* tp = g_t + (mrow + hrow * 8) * ND + col;
                    float2 t2 = *(float2*)tp;
                    t2.x += acc[mi][ni][hrow * 2];
                    t2.y += acc[mi][ni][hrow * 2 + 1];
                    if (MODE == 3) { t2.x += x0[col]; t2.y += x0[col + 1]; }
                    *(float2*)tp = t2;
                }
            }
    } else if (MODE == 2) {
#pragma unroll
        for (int mi = 0; mi < 2; mi++)
#pragma unroll
            for (int ni = 0; ni < 8; ni++) {
                long long mrow = aRow0 + wm * 32 + mi * 16 + r_in;
                int col = n0 + wn * 64 + ni * 8 + c_in;
                float bb0 = x0[col], bb1 = x0[col + 1];
#pragma unroll
                for (int hrow = 0; hrow < 2; hrow++) {
                    float v0 = acc[mi][ni][hrow * 2] + bb0;
                    float v1 = acc[mi][ni][hrow * 2 + 1] + bb1;
                    v0 = v0 > 0.f ? v0 : 0.01f * v0;
                    v1 = v1 > 0.f ? v1 : 0.01f * v1;
                    __nv_bfloat162 ph;
                    ph.x = __float2bfloat16(v0);
                    ph.y = __float2bfloat16(v1);
                    *(__nv_bfloat162*)&g_hidhi[(mrow + hrow * 8) * NH + col] = ph;
                }
            }
    } else {  // MODE 4
#pragma unroll
        for (int mi = 0; mi < 2; mi++)
#pragma unroll
            for (int ni = 0; ni < 8; ni++) {
                long long m = aRow0 + wm * 32 + mi * 16 + r_in;
                int col = n0 + wn * 64 + ni * 8 + c_in;
                float cb0 = x0[col], cb1 = x0[col + 1];
#pragma unroll
                for (int hrow = 0; hrow < 2; hrow++) {
                    long long mm = m + hrow * 8;
                    long long b = mm >> 10;
                    int p = (int)(mm & 1023);
                    float* tp = g_t + (b * NTP + 1 + p) * ND + col;
                    const float* pp = x1 + (long long)(1 + p) * ND + col;
                    tp[0] = acc[mi][ni][hrow * 2]     + cb0 + pp[0];
                    tp[1] = acc[mi][ni][hrow * 2 + 1] + cb1 + pp[1];
                }
            }
    }
}

// ---------------- fills ----------------
__global__ void fill_bd() {
    int i = blockIdx.x, j = threadIdx.x;
    int r = ((i & 255) * j) & 255;
    float s, c;
    sincospif(2.0f * (float)r / 256.0f, &s, &c);
    split2(i < ND ? c : s, &g_Bdhi[i * ND + j], &g_Bdlo[i * ND + j]);
}
__global__ void fill_cn() {
    int m = blockIdx.x;
    for (int k = threadIdx.x; k < KMIX; k += 256) {
        int half = (k < NTP);
        int kk = half ? k : k - NTP;
        float v = 0.f;
        if (m < NTOK && kk < NTOK) {
            int r = (int)(((long long)m * kk) % NTOK);
            float s, c;
            sincospif(2.0f * (float)r / (float)NTOK, &s, &c);
            v = half ? c : s;
        }
        split2(v, &g_Cnhi[(long long)m * KMIX + k], &g_Cnlo[(long long)m * KMIX + k]);
    }
}
__global__ void fill_wp(const float* __restrict__ w) {
    int n = blockIdx.x;
    for (int k = threadIdx.x; k < KPE; k += 256)
        split2(w[(long long)n * KPE + k], &g_wphi[n * KPE + k], &g_wplo[n * KPE + k]);
}
__global__ void fill_w1t(const float* __restrict__ w) {   // grid (NH, L), block 256
    int n = blockIdx.x, i = blockIdx.y, k = threadIdx.x;
    g_w1thi[((long long)i * NH + n) * ND + k] =
        __float2bfloat16(w[((long long)i * ND + k) * NH + n]);
}
__global__ void fill_w2t(const float* __restrict__ w) {   // grid (ND, L), block 256
    int n = blockIdx.x, i = blockIdx.y;
    for (int k = threadIdx.x; k < NH; k += 256)
        g_w2thi[((long long)i * ND + n) * NH + k] =
            __float2bfloat16(w[((long long)i * NH + k) * ND + n]);
}
__global__ void patch_gather(const float* __restrict__ x) {
    int m = blockIdx.x;
    int b = m >> 10, p = m & 1023;
    int gh = p >> 5, gw = p & 31;
    for (int k = threadIdx.x; k < KPE; k += 256) {
        int cch = k >> 8, rem = k & 255, rr = rem >> 4, q = rem & 15;
        float v = x[(((long long)b * 3 + cch) * 512 + gh * 16 + rr) * 512 + gw * 16 + q];
        split2(v, &g_pahi[(long long)m * KPE + k], &g_palo[(long long)m * KPE + k]);
    }
}
__global__ void cls_init(const float* __restrict__ cls, const float* __restrict__ pos) {
    g_t[(long long)blockIdx.x * NTP * ND + threadIdx.x] = cls[threadIdx.x] + pos[threadIdx.x];
}

// ---------------- LN + split ----------------
__device__ __forceinline__ float warp_sum(float v) {
#pragma unroll
    for (int o = 16; o > 0; o >>= 1) v += __shfl_xor_sync(0xffffffffu, v, o);
    return v;
}
__device__ __forceinline__ float warp_max(float v) {
#pragma unroll
    for (int o = 16; o > 0; o >>= 1) v = fmaxf(v, __shfl_xor_sync(0xffffffffu, v, o));
    return v;
}
__global__ void ln_split(const float* __restrict__ gam, const float* __restrict__ bet) {
    int tid = threadIdx.x, wid = tid >> 5, lane = tid & 31;
    long long row = (long long)blockIdx.x * 8 + wid;
    long long o = row * ND + lane * 8;
    if ((int)(row % NTP) >= NTOK) {
        uint4 zz = make_uint4(0, 0, 0, 0);
        *(uint4*)(g_hhi + o) = zz;
        *(uint4*)(g_hlo + o) = zz;
        return;
    }
    float v[8];
    float4 a = *(const float4*)(g_t + o), b = *(const float4*)(g_t + o + 4);
    v[0]=a.x; v[1]=a.y; v[2]=a.z; v[3]=a.w; v[4]=b.x; v[5]=b.y; v[6]=b.z; v[7]=b.w;
    float s = 0.f;
#pragma unroll
    for (int k = 0; k < 8; k++) s += v[k];
    float mean = warp_sum(s) * (1.f / 256.f);
    float q = 0.f;
#pragma unroll
    for (int k = 0; k < 8; k++) { float d = v[k] - mean; q += d * d; }
    float rstd = rsqrtf(warp_sum(q) * (1.f / 256.f) + 1e-5f);
    float4 g0 = *(const float4*)(gam + lane * 8), g1 = *(const float4*)(gam + lane * 8 + 4);
    float4 b0 = *(const float4*)(bet + lane * 8), b1 = *(const float4*)(bet + lane * 8 + 4);
    float gg[8] = {g0.x,g0.y,g0.z,g0.w,g1.x,g1.y,g1.z,g1.w};
    float bb[8] = {b0.x,b0.y,b0.z,b0.w,b1.x,b1.y,b1.z,b1.w};
#pragma unroll
    for (int k = 0; k < 8; k++)
        split2((v[k] - mean) * rstd * gg[k] + bb[k], &g_hhi[o + k], &g_hlo[o + k]);
}

// ---------------- pool + head ----------------
__global__ void pool_kernel() {
    int b = blockIdx.x, d = threadIdx.x;
    const float* p = g_t + (long long)b * NTP * ND + d;
    float s = 0.f;
#pragma unroll 8
    for (int n = 0; n < NTOK; n++) s += p[(long long)n * ND];
    g_pooled[b * ND + d] = s * (1.f / 1025.f);
}
__device__ float block_sum(float v, float* sbuf) {
    int tid = threadIdx.x;
    float w = warp_sum(v);
    if ((tid & 31) == 0) sbuf[tid >> 5] = w;
    __syncthreads();
    float r = (tid < 8) ? sbuf[tid] : 0.f;
    if (tid < 32) { r = warp_sum(r); if (tid == 0) sbuf[0] = r; }
    __syncthreads();
    float res = sbuf[0];
    __syncthreads();
    return res;
}
__device__ float block_max(float v, float* sbuf) {
    int tid = threadIdx.x;
    float w = warp_max(v);
    if ((tid & 31) == 0) sbuf[tid >> 5] = w;
    __syncthreads();
    float r = (tid < 8) ? sbuf[tid] : -3.4e38f;
    if (tid < 32) { r = warp_max(r); if (tid == 0) sbuf[0] = r; }
    __syncthreads();
    float res = sbuf[0];
    __syncthreads();
    return res;
}
__global__ void head_kernel(const float* __restrict__ hw, const float* __restrict__ hb,
                            const float* __restrict__ gs, const float* __restrict__ gb,
                            float* __restrict__ out) {
    __shared__ float sbuf[32];
    __shared__ float lnp[256];
    int b = blockIdx.x, tid = threadIdx.x;
    float v = g_pooled[b * ND + tid];
    float mean = block_sum(v, sbuf) * (1.f / 256.f);
    float d = v - mean;
    float var = block_sum(d * d, sbuf) * (1.f / 256.f);
    lnp[tid] = d * rsqrtf(var + 1e-5f) * gs[tid] + gb[tid];
    __syncthreads();
    float lg[4];
#pragma unroll
    for (int j = 0; j < 4; j++) {
        int n = tid + j * 256;
        float s = -3.4e38f;
        if (n < NCLS) {
            s = hb[n];
            for (int k = 0; k < ND; k++) s = fmaf(lnp[k], hw[k * NCLS + n], s);
        }
        lg[j] = s;
    }
    float mx = block_max(fmaxf(fmaxf(lg[0], lg[1]), fmaxf(lg[2], lg[3])), sbuf);
    float es = 0.f;
#pragma unroll
    for (int j = 0; j < 4; j++) {
        int n = tid + j * 256;
        if (n < NCLS) { lg[j] = expf(lg[j] - mx); es += lg[j]; }
    }
    float inv = 1.f / block_sum(es, sbuf);
#pragma unroll
    for (int j = 0; j < 4; j++) {
        int n = tid + j * 256;
        if (n < NCLS) out[(long long)b * NCLS + n] = lg[j] * inv;
    }
}

// ---------------- host ----------------
extern "C" void kernel_launch(void* const* d_in, const int* in_sizes, int n_in,
                              void* d_out, int out_size) {
    const float* x      = (const float*)d_in[0];
    const float* conv_w = (const float*)d_in[1];
    const float* conv_b = (const float*)d_in[2];
    const float* pos    = (const float*)d_in[3];
    const float* cls    = (const float*)d_in[4];
    const float* ln1_s  = (const float*)d_in[5];
    const float* ln1_b  = (const float*)d_in[6];
    const float* ln2_s  = (const float*)d_in[7];
    const float* ln2_b  = (const float*)d_in[8];
    const float* w1     = (const float*)d_in[9];
    const float* b1     = (const float*)d_in[10];
    const float* w2     = (const float*)d_in[11];
    const float* b2     = (const float*)d_in[12];
    const float* hls    = (const float*)d_in[13];
    const float* hlb    = (const float*)d_in[14];
    const float* hw     = (const float*)d_in[15];
    const float* hb     = (const float*)d_in[16];
    float* out = (float*)d_out;

    cudaFuncSetAttribute(gemm_mma<0>, cudaFuncAttributeMaxDynamicSharedMemorySize, CF<0>::DSMB);
    cudaFuncSetAttribute(gemm_mma<1>, cudaFuncAttributeMaxDynamicSharedMemorySize, CF<1>::DSMB);
    cudaFuncSetAttribute(gemm_mma<2>, cudaFuncAttributeMaxDynamicSharedMemorySize, CF<2>::DSMB);
    cudaFuncSetAttribute(gemm_mma<3>, cudaFuncAttributeMaxDynamicSharedMemorySize, CF<3>::DSMB);
    cudaFuncSetAttribute(gemm_mma<4>, cudaFuncAttributeMaxDynamicSharedMemorySize, CF<4>::DSMB);

    fill_bd<<<512, 256>>>();
    fill_cn<<<NTP, 256>>>();
    fill_wp<<<256, 256>>>(conv_w);
    fill_w1t<<<dim3(NH, L), 256>>>(w1);
    fill_w2t<<<dim3(ND, L), 256>>>(w2);
    patch_gather<<<MPE, 256>>>(x);
    cls_init<<<NB, 256>>>(cls, pos);
    gemm_mma<4><<<dim3(MPE / 128, ND / 128, 1), 256, CF<4>::DSMB>>>(conv_b, pos, 0);

    for (int i = 0; i < 6; i++) {
        ln_split<<<MROWS / 8, 256>>>(ln1_s + (size_t)i * ND, ln1_b + (size_t)i * ND);
        gemm_mma<0><<<dim3(4, NTP / 128, NB), 256, CF<0>::DSMB>>>(nullptr, nullptr, i);
        gemm_mma<1><<<dim3(NTP / 128, ND / 128, NB), 256, CF<1>::DSMB>>>(nullptr, nullptr, i);
        ln_split<<<MROWS / 8, 256>>>(ln2_s + (size_t)i * ND, ln2_b + (size_t)i * ND);
        gemm_mma<2><<<dim3(MROWS / 128, NH / 128, 1), 256, CF<2>::DSMB>>>(b1 + (size_t)i * NH, nullptr, i);
        gemm_mma<3><<<dim3(MROWS / 128, ND / 128, 1), 256, CF<3>::DSMB>>>(b2 + (size_t)i * ND, nullptr, i);
    }

    pool_kernel<<<NB, 256>>>();
    head_kernel<<<NB, 256>>>(hw, hb, hls, hlb, out);
}

// round 10
// speedup vs baseline: 3.7269x; 1.2640x over previous
#include <cuda_runtime.h>
#include <cuda_bf16.h>
#include <cstdint>

#define NTP   1152
#define NTOK  1025
#define ND    256
#define NH    1024
#define NCLS  1000
#define NB    64
#define MROWS (NB*NTP)
#define KPE   768
#define MPE   (NB*1024)
#define L     6

// ---------------- static scratch ----------------
__device__ float          g_t    [(long long)MROWS*ND];
__device__ float          g_pooled[NB*ND];
__device__ float          g_mix  [(long long)MROWS*ND];     // Mc|Ms per token row
__device__ float          g_mix0 [MROWS];                   // dim-0 mixing result
__device__ float          g_u0   [MROWS];                   // rowsum of LN output
__device__ float          g_Cnf  [(long long)NTP*NTP];      // fp32 cos DFT (symmetric)
__device__ __nv_bfloat16  g_hhi  [(long long)MROWS*ND];
__device__ __nv_bfloat16  g_hlo  [(long long)MROWS*ND];
__device__ __nv_bfloat16  g_Phi  [(long long)NB*256*NTP];   // [b][r:128U+128V][tok]
__device__ __nv_bfloat16  g_Plo  [(long long)NB*256*NTP];
__device__ __nv_bfloat16  g_hidhi[(long long)MROWS*NH];
__device__ __nv_bfloat16  g_Cnh  [(long long)NTP*NTP];
__device__ __nv_bfloat16  g_Cnl  [(long long)NTP*NTP];
__device__ __nv_bfloat16  g_Snh  [(long long)NTP*NTP];
__device__ __nv_bfloat16  g_Snl  [(long long)NTP*NTP];
__device__ __nv_bfloat16  g_Bdhi [256*ND];                  // [Cd d=1..128 ; Sd d=1..128]
__device__ __nv_bfloat16  g_Bdlo [256*ND];
__device__ __nv_bfloat16  g_w1thi[(long long)L*NH*ND];
__device__ __nv_bfloat16  g_w2thi[(long long)L*ND*NH];
__device__ __nv_bfloat16  g_wphi [ND*KPE];
__device__ __nv_bfloat16  g_wplo [ND*KPE];
__device__ __nv_bfloat16  g_pahi [(long long)MPE*KPE];
__device__ __nv_bfloat16  g_palo [(long long)MPE*KPE];

// ---------------- helpers ----------------
__device__ __forceinline__ uint32_t smem_to_u32(const void* p) {
    uint32_t a;
    asm("{ .reg .u64 t; cvta.to.shared.u64 t, %1; cvt.u32.u64 %0, t; }" : "=r"(a) : "l"(p));
    return a;
}
__device__ __forceinline__ void split2(float v, __nv_bfloat16* hi, __nv_bfloat16* lo) {
    __nv_bfloat16 h = __float2bfloat16(v);
    *hi = h;
    *lo = __float2bfloat16(v - __bfloat162float(h));
}

#define LDSM4(r, addr) \
    asm volatile("ldmatrix.sync.aligned.m8n8.x4.shared.b16 {%0,%1,%2,%3}, [%4];" \
                 : "=r"((r)[0]), "=r"((r)[1]), "=r"((r)[2]), "=r"((r)[3]) : "r"(addr))

#define MMA(d, a, b) \
    asm volatile("mma.sync.aligned.m16n8k16.row.col.f32.bf16.bf16.f32 " \
                 "{%0,%1,%2,%3},{%4,%5,%6,%7},{%8,%9},{%0,%1,%2,%3};" \
                 : "+f"((d)[0]), "+f"((d)[1]), "+f"((d)[2]), "+f"((d)[3]) \
                 : "r"((a)[0]), "r"((a)[1]), "r"((a)[2]), "r"((a)[3]), "r"((b)[0]), "r"((b)[1]))

#define CP16(dst, src) \
    asm volatile("cp.async.cg.shared.global [%0], [%1], 16;" :: "r"(dst), "l"(src))
#define CP_COMMIT() asm volatile("cp.async.commit_group;" ::: "memory")
#define CP_WAIT0()  asm volatile("cp.async.wait_group 0;" ::: "memory")
#define CP_WAIT1()  asm volatile("cp.async.wait_group 1;" ::: "memory")

// ---------------- GEMM engine ----------------
// BM=128, BN=128, BK=64; 256 threads, 8 warps (4m x 2n), warp tile 32x64.
// A: [M][K] bf16; B: [N][K] bf16 (K contiguous). D = A*B^T (fp32 accum).
// MODE 0: A=BdN(256x256) B=h[b] -> P (U,V transposed)                [SPLIT]
// MODE 1: A=Cn or Sn (by n-tile) B=P half, K=1152 -> g_mix (write)   [SPLIT]
// MODE 2: A=h(hi) B=w1t[li] K=256  -> leaky(D+b1) -> hidhi           [plain]
// MODE 3: A=hidhi B=w2t[li] K=1024 -> t += D + b2                    [plain]
// MODE 4: A=pa B=wp K=768 -> t = D + conv_b + pos                    [SPLIT]
#define STR 72
#define TILE_H (128*STR)

template<int MODE> struct CF {
    static constexpr int K     = (MODE == 1) ? NTP : (MODE == 3) ? NH : (MODE == 4) ? KPE : ND;
    static constexpr int NCH   = K / 64;
    static constexpr int SPLIT = (MODE == 2 || MODE == 3) ? 0 : 1;
    static constexpr int NTIL  = SPLIT ? 4 : 2;
    static constexpr int STB   = NTIL * TILE_H * 2;
    static constexpr int DSMB  = 2 * STB;
};

__device__ __forceinline__ void load4(uint32_t sbase, const __nv_bfloat16* __restrict__ g,
                                      int K, int k0, int tid) {
#pragma unroll
    for (int i = 0; i < 4; i++) {
        int idx = tid + (i << 8);
        int row = idx >> 3, c8 = (idx & 7) << 3;
        uint32_t d = sbase + (uint32_t)((row * STR + c8) << 1);
        const __nv_bfloat16* gp = g + (long long)row * K + k0 + c8;
        CP16(d, gp);
    }
}

template<int MODE>
__global__ void __launch_bounds__(256, 1)
gemm_mma(const float* __restrict__ x0, const float* __restrict__ x1, int li) {
    constexpr int K = CF<MODE>::K, NCH = CF<MODE>::NCH;
    constexpr int SPLIT = CF<MODE>::SPLIT;
    constexpr int STB = CF<MODE>::STB;
    constexpr uint32_t OF_AH = 0;
    constexpr uint32_t OF_AL = TILE_H * 2;
    constexpr uint32_t OF_BH = (SPLIT ? 2 : 1) * TILE_H * 2;
    constexpr uint32_t OF_BL = 3 * TILE_H * 2;

    extern __shared__ char dsm[];
    uint32_t sb = smem_to_u32(dsm);
    int tid = threadIdx.x, wid = tid >> 5, lid = tid & 31;
    int wm = wid & 3, wn = wid >> 2;
    int n0 = blockIdx.y << 7, z = blockIdx.z;
    long long aRow0 = (long long)blockIdx.x << 7;

    const __nv_bfloat16 *Ahi, *Alo = nullptr, *Bhi, *Blo = nullptr;
    if      (MODE == 0) { Ahi = g_Bdhi + aRow0 * K;  Alo = g_Bdlo + aRow0 * K;
                          long long r = (long long)z * NTP + n0;
                          Bhi = g_hhi + r * K;       Blo = g_hlo + r * K; }
    else if (MODE == 1) { Ahi = (n0 ? g_Snh : g_Cnh) + aRow0 * K;
                          Alo = (n0 ? g_Snl : g_Cnl) + aRow0 * K;
                          long long r = ((long long)z * 256 + n0) * K;
                          Bhi = g_Phi + r;           Blo = g_Plo + r; }
    else if (MODE == 2) { Ahi = g_hhi + aRow0 * K;
                          Bhi = g_w1thi + ((long long)li * NH + n0) * K; }
    else if (MODE == 3) { Ahi = g_hidhi + aRow0 * K;
                          Bhi = g_w2thi + ((long long)li * ND + n0) * K; }
    else                { Ahi = g_pahi + aRow0 * K;  Alo = g_palo + aRow0 * K;
                          Bhi = g_wphi + (long long)n0 * K;
                          Blo = g_wplo + (long long)n0 * K; }

    float acc[2][8][4];
#pragma unroll
    for (int i = 0; i < 2; i++)
#pragma unroll
        for (int j = 0; j < 8; j++)
#pragma unroll
            for (int q = 0; q < 4; q++) acc[i][j][q] = 0.f;

    int a_r = lid & 15, a_c = (lid >> 4) << 3;
    int b_grp = lid >> 3, b_w = lid & 7;
    int b_roff = ((b_grp >> 1) << 3) + b_w, b_coff = (b_grp & 1) << 3;

    {
        load4(sb + OF_AH, Ahi, K, 0, tid);
        if (SPLIT) load4(sb + OF_AL, Alo, K, 0, tid);
        load4(sb + OF_BH, Bhi, K, 0, tid);
        if (SPLIT) load4(sb + OF_BL, Blo, K, 0, tid);
        CP_COMMIT();
    }

    for (int c = 0; c < NCH; c++) {
        if (c + 1 < NCH) {
            uint32_t s1 = sb + ((c + 1) & 1) * STB;
            int k0 = (c + 1) << 6;
            load4(s1 + OF_AH, Ahi, K, k0, tid);
            if (SPLIT) load4(s1 + OF_AL, Alo, K, k0, tid);
            load4(s1 + OF_BH, Bhi, K, k0, tid);
            if (SPLIT) load4(s1 + OF_BL, Blo, K, k0, tid);
            CP_COMMIT();
            CP_WAIT1();
        } else {
            CP_WAIT0();
        }
        __syncthreads();
        uint32_t sc = sb + (c & 1) * STB;
#pragma unroll
        for (int ks = 0; ks < 4; ks++) {
            uint32_t ah[2][4], al[2][4], bh[8][2], bl[8][2];
#pragma unroll
            for (int mi = 0; mi < 2; mi++) {
                uint32_t off = (uint32_t)(((wm * 32 + mi * 16 + a_r) * STR + ks * 16 + a_c) << 1);
                LDSM4(ah[mi], sc + OF_AH + off);
                if (SPLIT) LDSM4(al[mi], sc + OF_AL + off);
            }
#pragma unroll
            for (int nj = 0; nj < 4; nj++) {
                uint32_t off = (uint32_t)(((wn * 64 + nj * 16 + b_roff) * STR + ks * 16 + b_coff) << 1);
                uint32_t r4[4];
                LDSM4(r4, sc + OF_BH + off);
                bh[nj * 2][0] = r4[0]; bh[nj * 2][1] = r4[1];
                bh[nj * 2 + 1][0] = r4[2]; bh[nj * 2 + 1][1] = r4[3];
                if (SPLIT) {
                    LDSM4(r4, sc + OF_BL + off);
                    bl[nj * 2][0] = r4[0]; bl[nj * 2][1] = r4[1];
                    bl[nj * 2 + 1][0] = r4[2]; bl[nj * 2 + 1][1] = r4[3];
                }
            }
#pragma unroll
            for (int mi = 0; mi < 2; mi++)
#pragma unroll
                for (int ni = 0; ni < 8; ni++) {
                    MMA(acc[mi][ni], ah[mi], bh[ni]);
                    if (SPLIT) {
                        MMA(acc[mi][ni], ah[mi], bl[ni]);
                        MMA(acc[mi][ni], al[mi], bh[ni]);
                    }
                }
        }
        __syncthreads();
    }

    // ---------------- epilogue ----------------
    int r_in = lid >> 2, c_in = (lid & 3) << 1;

    if (MODE == 0) {
        // write P[b][r][tok] (bf16 split, no sign: combine applies -Ms)
#pragma unroll
        for (int mi = 0; mi < 2; mi++)
#pragma unroll
            for (int ni = 0; ni < 8; ni++) {
                int rbase = (int)aRow0 + wm * 32 + mi * 16 + r_in;
                int tok = n0 + wn * 64 + ni * 8 + c_in;
#pragma unroll
                for (int hrow = 0; hrow < 2; hrow++) {
                    int r = rbase + hrow * 8;
                    long long off = ((long long)z * 256 + r) * NTP + tok;
                    __nv_bfloat16 h0, l0, h1, l1;
                    split2(acc[mi][ni][hrow * 2],     &h0, &l0);
                    split2(acc[mi][ni][hrow * 2 + 1], &h1, &l1);
                    __nv_bfloat162 ph; ph.x = h0; ph.y = h1;
                    __nv_bfloat162 pl; pl.x = l0; pl.y = l1;
                    *(__nv_bfloat162*)&g_Phi[off] = ph;
                    *(__nv_bfloat162*)&g_Plo[off] = pl;
                }
            }
    } else if (MODE == 1) {
        // write-only fp32 Mc|Ms scratch
#pragma unroll
        for (int mi = 0; mi < 2; mi++)
#pragma unroll
            for (int ni = 0; ni < 8; ni++) {
                long long mrow = (long long)z * NTP + aRow0 + wm * 32 + mi * 16 + r_in;
                int col = n0 + wn * 64 + ni * 8 + c_in;
#pragma unroll
                for (int hrow = 0; hrow < 2; hrow++) {
                    float2 t2;
                    t2.x = acc[mi][ni][hrow * 2];
                    t2.y = acc[mi][ni][hrow * 2 + 1];
                    *(float2*)&g_mix[(mrow + hrow * 8) * ND + col] = t2;
                }
            }
    } else if (MODE == 3) {
#pragma unroll
        for (int mi = 0; mi < 2; mi++)
#pragma unroll
            for (int ni = 0; ni < 8; ni++) {
                long long mrow = aRow0 + wm * 32 + mi * 16 + r_in;
                int col = n0 + wn * 64 + ni * 8 + c_in;
#pragma unroll
                for (int hrow = 0; hrow < 2; hrow++) {
                    float* tp = g_t + (mrow + hrow * 8) * ND + col;
                    float2 t2 = *(float2*)tp;
                    t2.x += acc[mi][ni][hrow * 2]     + x0[col];
                    t2.y += acc[mi][ni][hrow * 2 + 1] + x0[col + 1];
                    *(float2*)tp = t2;
                }
            }
    } else if (MODE == 2) {
#pragma unroll
        for (int mi = 0; mi < 2; mi++)
#pragma unroll
            for (int ni = 0; ni < 8; ni++) {
                long long mrow = aRow0 + wm * 32 + mi * 16 + r_in;
                int col = n0 + wn * 64 + ni * 8 + c_in;
                float bb0 = x0[col], bb1 = x0[col + 1];
#pragma unroll
                for (int hrow = 0; hrow < 2; hrow++) {
                    float v0 = acc[mi][ni][hrow * 2] + bb0;
                    float v1 = acc[mi][ni][hrow * 2 + 1] + bb1;
                    v0 = v0 > 0.f ? v0 : 0.01f * v0;
                    v1 = v1 > 0.f ? v1 : 0.01f * v1;
                    __nv_bfloat162 ph;
                    ph.x = __float2bfloat16(v0);
                    ph.y = __float2bfloat16(v1);
                    *(__nv_bfloat162*)&g_hidhi[(mrow + hrow * 8) * NH + col] = ph;
                }
            }
    } else {  // MODE 4
#pragma unroll
        for (int mi = 0; mi < 2; mi++)
#pragma unroll
            for (int ni = 0; ni < 8; ni++) {
                long long m = aRow0 + wm * 32 + mi * 16 + r_in;
                int col = n0 + wn * 64 + ni * 8 + c_in;
                float cb0 = x0[col], cb1 = x0[col + 1];
#pragma unroll
                for (int hrow = 0; hrow < 2; hrow++) {
                    long long mm = m + hrow * 8;
                    long long b = mm >> 10;
                    int p = (int)(mm & 1023);
                    float* tp = g_t + (b * NTP + 1 + p) * ND + col;
                    const float* pp = x1 + (long long)(1 + p) * ND + col;
                    tp[0] = acc[mi][ni][hrow * 2]     + cb0 + pp[0];
                    tp[1] = acc[mi][ni][hrow * 2 + 1] + cb1 + pp[1];
                }
            }
    }
}

// ---------------- dim-0 mixing: g_mix0 = Cn * u0 (fp32) ----------------
__global__ void gemm0_kernel() {   // grid (NTP/128, NB), block 128
    __shared__ float su[NTP];
    int b = blockIdx.y;
    int t0 = blockIdx.x * 128 + threadIdx.x;
    for (int k = threadIdx.x; k < NTP; k += 128) su[k] = g_u0[b * NTP + k];
    __syncthreads();
    float acc = 0.f;
#pragma unroll 8
    for (int k = 0; k < NTOK; k++)
        acc += g_Cnf[(long long)k * NTP + t0] * su[k];
    g_mix0[b * NTP + t0] = acc;
}

// ---------------- combine: t += symmetric reconstruction ----------------
__global__ void combine_kernel() {   // grid MROWS, block 256
    __shared__ float sh[256];
    long long row = blockIdx.x;
    int d = threadIdx.x;
    sh[d] = g_mix[row * ND + d];
    __syncthreads();
    float add;
    if (d == 0)        add = g_mix0[row];
    else if (d <= 128) add = sh[d - 1] - sh[127 + d];
    else { int dp = 256 - d; add = sh[dp - 1] + sh[127 + dp]; }
    g_t[row * ND + d] += add;
}

// ---------------- fills ----------------
__global__ void fill_bd() {            // grid 256, block 256
    int i = blockIdx.x, j = threadIdx.x;
    int dim = (i & 127) + 1;
    int r = (dim * j) & 255;
    float s, c;
    sincospif(2.0f * (float)r / 256.0f, &s, &c);
    split2(i < 128 ? c : s, &g_Bdhi[i * ND + j], &g_Bdlo[i * ND + j]);
}
__global__ void fill_cn() {            // grid NTP, block 256
    int m = blockIdx.x;
    for (int k = threadIdx.x; k < NTP; k += 256) {
        float vc = 0.f, vs = 0.f;
        if (m < NTOK && k < NTOK) {
            int r = (int)(((long long)m * k) % NTOK);
            sincospif(2.0f * (float)r / (float)NTOK, &vs, &vc);
        }
        long long o = (long long)m * NTP + k;
        split2(vc, &g_Cnh[o], &g_Cnl[o]);
        split2(vs, &g_Snh[o], &g_Snl[o]);
        g_Cnf[o] = vc;
    }
}
__global__ void fill_wp(const float* __restrict__ w) {
    int n = blockIdx.x;
    for (int k = threadIdx.x; k < KPE; k += 256)
        split2(w[(long long)n * KPE + k], &g_wphi[n * KPE + k], &g_wplo[n * KPE + k]);
}
__global__ void fill_w1t(const float* __restrict__ w) {   // grid (NH, L)
    int n = blockIdx.x, i = blockIdx.y, k = threadIdx.x;
    g_w1thi[((long long)i * NH + n) * ND + k] =
        __float2bfloat16(w[((long long)i * ND + k) * NH + n]);
}
__global__ void fill_w2t(const float* __restrict__ w) {   // grid (ND, L)
    int n = blockIdx.x, i = blockIdx.y;
    for (int k = threadIdx.x; k < NH; k += 256)
        g_w2thi[((long long)i * ND + n) * NH + k] =
            __float2bfloat16(w[((long long)i * NH + k) * ND + n]);
}
__global__ void patch_gather(const float* __restrict__ x) {
    int m = blockIdx.x;
    int b = m >> 10, p = m & 1023;
    int gh = p >> 5, gw = p & 31;
    for (int k = threadIdx.x; k < KPE; k += 256) {
        int cch = k >> 8, rem = k & 255, rr = rem >> 4, q = rem & 15;
        float v = x[(((long long)b * 3 + cch) * 512 + gh * 16 + rr) * 512 + gw * 16 + q];
        split2(v, &g_pahi[(long long)m * KPE + k], &g_palo[(long long)m * KPE + k]);
    }
}
__global__ void cls_init(const float* __restrict__ cls, const float* __restrict__ pos) {
    g_t[(long long)blockIdx.x * NTP * ND + threadIdx.x] = cls[threadIdx.x] + pos[threadIdx.x];
}

// ---------------- LN + split (+ rowsum for dim-0 path) ----------------
__device__ __forceinline__ float warp_sum(float v) {
#pragma unroll
    for (int o = 16; o > 0; o >>= 1) v += __shfl_xor_sync(0xffffffffu, v, o);
    return v;
}
__device__ __forceinline__ float warp_max(float v) {
#pragma unroll
    for (int o = 16; o > 0; o >>= 1) v = fmaxf(v, __shfl_xor_sync(0xffffffffu, v, o));
    return v;
}
template<int U0>
__global__ void ln_split(const float* __restrict__ gam, const float* __restrict__ bet) {
    int tid = threadIdx.x, wid = tid >> 5, lane = tid & 31;
    long long row = (long long)blockIdx.x * 8 + wid;
    long long o = row * ND + lane * 8;
    if ((int)(row % NTP) >= NTOK) {
        uint4 zz = make_uint4(0, 0, 0, 0);
        *(uint4*)(g_hhi + o) = zz;
        *(uint4*)(g_hlo + o) = zz;
        if (U0 && lane == 0) g_u0[row] = 0.f;
        return;
    }
    float v[8];
    float4 a = *(const float4*)(g_t + o), b = *(const float4*)(g_t + o + 4);
    v[0]=a.x; v[1]=a.y; v[2]=a.z; v[3]=a.w; v[4]=b.x; v[5]=b.y; v[6]=b.z; v[7]=b.w;
    float s = 0.f;
#pragma unroll
    for (int k = 0; k < 8; k++) s += v[k];
    float mean = warp_sum(s) * (1.f / 256.f);
    float q = 0.f;
#pragma unroll
    for (int k = 0; k < 8; k++) { float d = v[k] - mean; q += d * d; }
    float rstd = rsqrtf(warp_sum(q) * (1.f / 256.f) + 1e-5f);
    float4 g0 = *(const float4*)(gam + lane * 8), g1 = *(const float4*)(gam + lane * 8 + 4);
    float4 b0 = *(const float4*)(bet + lane * 8), b1 = *(const float4*)(bet + lane * 8 + 4);
    float gg[8] = {g0.x,g0.y,g0.z,g0.w,g1.x,g1.y,g1.z,g1.w};
    float bb[8] = {b0.x,b0.y,b0.z,b0.w,b1.x,b1.y,b1.z,b1.w};
    float rs = 0.f;
#pragma unroll
    for (int k = 0; k < 8; k++) {
        float r = (v[k] - mean) * rstd * gg[k] + bb[k];
        if (U0) rs += r;
        split2(r, &g_hhi[o + k], &g_hlo[o + k]);
    }
    if (U0) {
        float tot = warp_sum(rs);
        if (lane == 0) g_u0[row] = tot;
    }
}

// ---------------- pool + head ----------------
__global__ void pool_kernel() {
    int b = blockIdx.x, d = threadIdx.x;
    const float* p = g_t + (long long)b * NTP * ND + d;
    float s = 0.f;
#pragma unroll 8
    for (int n = 0; n < NTOK; n++) s += p[(long long)n * ND];
    g_pooled[b * ND + d] = s * (1.f / 1025.f);
}
__device__ float block_sum(float v, float* sbuf) {
    int tid = threadIdx.x;
    float w = warp_sum(v);
    if ((tid & 31) == 0) sbuf[tid >> 5] = w;
    __syncthreads();
    float r = (tid < 8) ? sbuf[tid] : 0.f;
    if (tid < 32) { r = warp_sum(r); if (tid == 0) sbuf[0] = r; }
    __syncthreads();
    float res = sbuf[0];
    __syncthreads();
    return res;
}
__device__ float block_max(float v, float* sbuf) {
    int tid = threadIdx.x;
    float w = warp_max(v);
    if ((tid & 31) == 0) sbuf[tid >> 5] = w;
    __syncthreads();
    float r = (tid < 8) ? sbuf[tid] : -3.4e38f;
    if (tid < 32) { r = warp_max(r); if (tid == 0) sbuf[0] = r; }
    __syncthreads();
    float res = sbuf[0];
    __syncthreads();
    return res;
}
__global__ void head_kernel(const float* __restrict__ hw, const float* __restrict__ hb,
                            const float* __restrict__ gs, const float* __restrict__ gb,
                            float* __restrict__ out) {
    __shared__ float sbuf[32];
    __shared__ float lnp[256];
    int b = blockIdx.x, tid = threadIdx.x;
    float v = g_pooled[b * ND + tid];
    float mean = block_sum(v, sbuf) * (1.f / 256.f);
    float d = v - mean;
    float var = block_sum(d * d, sbuf) * (1.f / 256.f);
    lnp[tid] = d * rsqrtf(var + 1e-5f) * gs[tid] + gb[tid];
    __syncthreads();
    float lg[4];
#pragma unroll
    for (int j = 0; j < 4; j++) {
        int n = tid + j * 256;
        float s = -3.4e38f;
        if (n < NCLS) {
            s = hb[n];
            for (int k = 0; k < ND; k++) s = fmaf(lnp[k], hw[k * NCLS + n], s);
        }
        lg[j] = s;
    }
    float mx = block_max(fmaxf(fmaxf(lg[0], lg[1]), fmaxf(lg[2], lg[3])), sbuf);
    float es = 0.f;
#pragma unroll
    for (int j = 0; j < 4; j++) {
        int n = tid + j * 256;
        if (n < NCLS) { lg[j] = expf(lg[j] - mx); es += lg[j]; }
    }
    float inv = 1.f / block_sum(es, sbuf);
#pragma unroll
    for (int j = 0; j < 4; j++) {
        int n = tid + j * 256;
        if (n < NCLS) out[(long long)b * NCLS + n] = lg[j] * inv;
    }
}

// ---------------- host ----------------
extern "C" void kernel_launch(void* const* d_in, const int* in_sizes, int n_in,
                              void* d_out, int out_size) {
    const float* x      = (const float*)d_in[0];
    const float* conv_w = (const float*)d_in[1];
    const float* conv_b = (const float*)d_in[2];
    const float* pos    = (const float*)d_in[3];
    const float* cls    = (const float*)d_in[4];
    const float* ln1_s  = (const float*)d_in[5];
    const float* ln1_b  = (const float*)d_in[6];
    const float* ln2_s  = (const float*)d_in[7];
    const float* ln2_b  = (const float*)d_in[8];
    const float* w1     = (const float*)d_in[9];
    const float* b1     = (const float*)d_in[10];
    const float* w2     = (const float*)d_in[11];
    const float* b2     = (const float*)d_in[12];
    const float* hls    = (const float*)d_in[13];
    const float* hlb    = (const float*)d_in[14];
    const float* hw     = (const float*)d_in[15];
    const float* hb     = (const float*)d_in[16];
    float* out = (float*)d_out;

    cudaFuncSetAttribute(gemm_mma<0>, cudaFuncAttributeMaxDynamicSharedMemorySize, CF<0>::DSMB);
    cudaFuncSetAttribute(gemm_mma<1>, cudaFuncAttributeMaxDynamicSharedMemorySize, CF<1>::DSMB);
    cudaFuncSetAttribute(gemm_mma<2>, cudaFuncAttributeMaxDynamicSharedMemorySize, CF<2>::DSMB);
    cudaFuncSetAttribute(gemm_mma<3>, cudaFuncAttributeMaxDynamicSharedMemorySize, CF<3>::DSMB);
    cudaFuncSetAttribute(gemm_mma<4>, cudaFuncAttributeMaxDynamicSharedMemorySize, CF<4>::DSMB);

    fill_bd<<<256, 256>>>();
    fill_cn<<<NTP, 256>>>();
    fill_wp<<<256, 256>>>(conv_w);
    fill_w1t<<<dim3(NH, L), 256>>>(w1);
    fill_w2t<<<dim3(ND, L), 256>>>(w2);
    patch_gather<<<MPE, 256>>>(x);
    cls_init<<<NB, 256>>>(cls, pos);
    gemm_mma<4><<<dim3(MPE / 128, ND / 128, 1), 256, CF<4>::DSMB>>>(conv_b, pos, 0);

    for (int i = 0; i < 6; i++) {
        ln_split<1><<<MROWS / 8, 256>>>(ln1_s + (size_t)i * ND, ln1_b + (size_t)i * ND);
        gemm_mma<0><<<dim3(2, NTP / 128, NB), 256, CF<0>::DSMB>>>(nullptr, nullptr, i);
        gemm_mma<1><<<dim3(NTP / 128, 2, NB), 256, CF<1>::DSMB>>>(nullptr, nullptr, i);
        gemm0_kernel<<<dim3(NTP / 128, NB), 128>>>();
        combine_kernel<<<MROWS, 256>>>();
        ln_split<0><<<MROWS / 8, 256>>>(ln2_s + (size_t)i * ND, ln2_b + (size_t)i * ND);
        gemm_mma<2><<<dim3(MROWS / 128, NH / 128, 1), 256, CF<2>::DSMB>>>(b1 + (size_t)i * NH, nullptr, i);
        gemm_mma<3><<<dim3(MROWS / 128, ND / 128, 1), 256, CF<3>::DSMB>>>(b2 + (size_t)i * ND, nullptr, i);
    }

    pool_kernel<<<NB, 256>>>();
    head_kernel<<<NB, 256>>>(hw, hb, hls, hlb, out);
}

// round 13
// speedup vs baseline: 4.2568x; 1.1422x over previous
#include <cuda_runtime.h>
#include <cuda_bf16.h>
#include <cstdint>

#define NTP   1152
#define NTOK  1025
#define ND    256
#define NH    1024
#define NCLS  1000
#define NB    64
#define MROWS (NB*NTP)
#define KPE   768
#define MPE   (NB*1024)
#define L     6
#define MIXM  640            // mix output rows kept: tokens 0..512 (+pad), 5*128

// ---------------- static scratch ----------------
__device__ float          g_t    [(long long)MROWS*ND];
__device__ float          g_pooled[NB*ND];
__device__ float          g_mix  [(long long)NB*MIXM*ND];   // Mc|Ms, tokens 0..512
__device__ float          g_mix0 [MROWS];                   // dim-0 mixing result
__device__ float          g_u0   [MROWS];                   // rowsum of LN output
__device__ float          g_Cnf  [(long long)NTP*NTP];      // fp32 cos DFT (symmetric)
__device__ __nv_bfloat16  g_hhi  [(long long)MROWS*ND];
__device__ __nv_bfloat16  g_hlo  [(long long)MROWS*ND];
__device__ __nv_bfloat16  g_Phi  [(long long)NB*256*NTP];   // [b][r:128U+128V][tok]
__device__ __nv_bfloat16  g_Plo  [(long long)NB*256*NTP];
__device__ __nv_bfloat16  g_hidhi[(long long)MROWS*NH];
__device__ __nv_bfloat16  g_Cnh  [(long long)NTP*NTP];
__device__ __nv_bfloat16  g_Cnl  [(long long)NTP*NTP];
__device__ __nv_bfloat16  g_Snh  [(long long)NTP*NTP];
__device__ __nv_bfloat16  g_Snl  [(long long)NTP*NTP];
__device__ __nv_bfloat16  g_Bdhi [256*ND];                  // [Cd d=1..128 ; Sd d=1..128]
__device__ __nv_bfloat16  g_Bdlo [256*ND];
__device__ __nv_bfloat16  g_w1thi[(long long)L*NH*ND];
__device__ __nv_bfloat16  g_w2thi[(long long)L*ND*NH];
__device__ __nv_bfloat16  g_wphi [ND*KPE];
__device__ __nv_bfloat16  g_wplo [ND*KPE];
__device__ __nv_bfloat16  g_pahi [(long long)MPE*KPE];
__device__ __nv_bfloat16  g_palo [(long long)MPE*KPE];

// ---------------- helpers ----------------
__device__ __forceinline__ uint32_t smem_to_u32(const void* p) {
    uint32_t a;
    asm("{ .reg .u64 t; cvta.to.shared.u64 t, %1; cvt.u32.u64 %0, t; }" : "=r"(a) : "l"(p));
    return a;
}
__device__ __forceinline__ void split2(float v, __nv_bfloat16* hi, __nv_bfloat16* lo) {
    __nv_bfloat16 h = __float2bfloat16(v);
    *hi = h;
    *lo = __float2bfloat16(v - __bfloat162float(h));
}

#define LDSM4(r, addr) \
    asm volatile("ldmatrix.sync.aligned.m8n8.x4.shared.b16 {%0,%1,%2,%3}, [%4];" \
                 : "=r"((r)[0]), "=r"((r)[1]), "=r"((r)[2]), "=r"((r)[3]) : "r"(addr))

#define MMA(d, a, b) \
    asm volatile("mma.sync.aligned.m16n8k16.row.col.f32.bf16.bf16.f32 " \
                 "{%0,%1,%2,%3},{%4,%5,%6,%7},{%8,%9},{%0,%1,%2,%3};" \
                 : "+f"((d)[0]), "+f"((d)[1]), "+f"((d)[2]), "+f"((d)[3]) \
                 : "r"((a)[0]), "r"((a)[1]), "r"((a)[2]), "r"((a)[3]), "r"((b)[0]), "r"((b)[1]))

#define CP16(dst, src) \
    asm volatile("cp.async.cg.shared.global [%0], [%1], 16;" :: "r"(dst), "l"(src))
#define CP_COMMIT() asm volatile("cp.async.commit_group;" ::: "memory")
#define CP_WAIT0()  asm volatile("cp.async.wait_group 0;" ::: "memory")
#define CP_WAIT1()  asm volatile("cp.async.wait_group 1;" ::: "memory")

// ---------------- GEMM engine ----------------
// BM=128, BN=128, BK=64; 256 threads, 8 warps (4m x 2n), warp tile 32x64.
// A: [M][K] bf16; B: [N][K] bf16 (K contiguous). D = A*B^T (fp32 accum).
// MODE 0: A=BdN(256x256) B=h[b] -> P (U,V transposed)                [SPLIT]
// MODE 1: A=Cn or Sn rows 0..639 B=P half, K=1152 -> g_mix (write)   [SPLIT]
// MODE 2: A=h(hi) B=w1t[li] K=256  -> leaky(D+b1) -> hidhi           [plain]
// MODE 3: A=hidhi B=w2t[li] K=1024 -> t += D + b2                    [plain]
// MODE 4: A=pa B=wp K=768 -> t = D + conv_b + pos                    [SPLIT]
#define STR 72
#define TILE_H (128*STR)

template<int MODE> struct CF {
    static constexpr int K     = (MODE == 1) ? NTP : (MODE == 3) ? NH : (MODE == 4) ? KPE : ND;
    static constexpr int NCH   = K / 64;
    static constexpr int SPLIT = (MODE == 2 || MODE == 3) ? 0 : 1;
    static constexpr int NTIL  = SPLIT ? 4 : 2;
    static constexpr int STB   = NTIL * TILE_H * 2;
    static constexpr int DSMB  = 2 * STB;
};

__device__ __forceinline__ void load4(uint32_t sbase, const __nv_bfloat16* __restrict__ g,
                                      int K, int k0, int tid) {
#pragma unroll
    for (int i = 0; i < 4; i++) {
        int idx = tid + (i << 8);
        int row = idx >> 3, c8 = (idx & 7) << 3;
        uint32_t d = sbase + (uint32_t)((row * STR + c8) << 1);
        const __nv_bfloat16* gp = g + (long long)row * K + k0 + c8;
        CP16(d, gp);
    }
}

template<int MODE>
__global__ void __launch_bounds__(256, 1)
gemm_mma(const float* __restrict__ x0, const float* __restrict__ x1, int li) {
    constexpr int K = CF<MODE>::K, NCH = CF<MODE>::NCH;
    constexpr int SPLIT = CF<MODE>::SPLIT;
    constexpr int STB = CF<MODE>::STB;
    constexpr uint32_t OF_AH = 0;
    constexpr uint32_t OF_AL = TILE_H * 2;
    constexpr uint32_t OF_BH = (SPLIT ? 2 : 1) * TILE_H * 2;
    constexpr uint32_t OF_BL = 3 * TILE_H * 2;

    extern __shared__ char dsm[];
    uint32_t sb = smem_to_u32(dsm);
    int tid = threadIdx.x, wid = tid >> 5, lid = tid & 31;
    int wm = wid & 3, wn = wid >> 2;
    int n0 = blockIdx.y << 7, z = blockIdx.z;
    long long aRow0 = (long long)blockIdx.x << 7;

    const __nv_bfloat16 *Ahi, *Alo = nullptr, *Bhi, *Blo = nullptr;
    if      (MODE == 0) { Ahi = g_Bdhi + aRow0 * K;  Alo = g_Bdlo + aRow0 * K;
                          long long r = (long long)z * NTP + n0;
                          Bhi = g_hhi + r * K;       Blo = g_hlo + r * K; }
    else if (MODE == 1) { Ahi = (n0 ? g_Snh : g_Cnh) + aRow0 * K;
                          Alo = (n0 ? g_Snl : g_Cnl) + aRow0 * K;
                          long long r = ((long long)z * 256 + n0) * K;
                          Bhi = g_Phi + r;           Blo = g_Plo + r; }
    else if (MODE == 2) { Ahi = g_hhi + aRow0 * K;
                          Bhi = g_w1thi + ((long long)li * NH + n0) * K; }
    else if (MODE == 3) { Ahi = g_hidhi + aRow0 * K;
                          Bhi = g_w2thi + ((long long)li * ND + n0) * K; }
    else                { Ahi = g_pahi + aRow0 * K;  Alo = g_palo + aRow0 * K;
                          Bhi = g_wphi + (long long)n0 * K;
                          Blo = g_wplo + (long long)n0 * K; }

    float acc[2][8][4];
#pragma unroll
    for (int i = 0; i < 2; i++)
#pragma unroll
        for (int j = 0; j < 8; j++)
#pragma unroll
            for (int q = 0; q < 4; q++) acc[i][j][q] = 0.f;

    int a_r = lid & 15, a_c = (lid >> 4) << 3;
    int b_grp = lid >> 3, b_w = lid & 7;
    int b_roff = ((b_grp >> 1) << 3) + b_w, b_coff = (b_grp & 1) << 3;

    {
        load4(sb + OF_AH, Ahi, K, 0, tid);
        if (SPLIT) load4(sb + OF_AL, Alo, K, 0, tid);
        load4(sb + OF_BH, Bhi, K, 0, tid);
        if (SPLIT) load4(sb + OF_BL, Blo, K, 0, tid);
        CP_COMMIT();
    }

    for (int c = 0; c < NCH; c++) {
        if (c + 1 < NCH) {
            uint32_t s1 = sb + ((c + 1) & 1) * STB;
            int k0 = (c + 1) << 6;
            load4(s1 + OF_AH, Ahi, K, k0, tid);
            if (SPLIT) load4(s1 + OF_AL, Alo, K, k0, tid);
            load4(s1 + OF_BH, Bhi, K, k0, tid);
            if (SPLIT) load4(s1 + OF_BL, Blo, K, k0, tid);
            CP_COMMIT();
            CP_WAIT1();
        } else {
            CP_WAIT0();
        }
        __syncthreads();
        uint32_t sc = sb + (c & 1) * STB;
#pragma unroll
        for (int ks = 0; ks < 4; ks++) {
            uint32_t ah[2][4], al[2][4], bh[8][2], bl[8][2];
#pragma unroll
            for (int mi = 0; mi < 2; mi++) {
                uint32_t off = (uint32_t)(((wm * 32 + mi * 16 + a_r) * STR + ks * 16 + a_c) << 1);
                LDSM4(ah[mi], sc + OF_AH + off);
                if (SPLIT) LDSM4(al[mi], sc + OF_AL + off);
            }
#pragma unroll
            for (int nj = 0; nj < 4; nj++) {
                uint32_t off = (uint32_t)(((wn * 64 + nj * 16 + b_roff) * STR + ks * 16 + b_coff) << 1);
                uint32_t r4[4];
                LDSM4(r4, sc + OF_BH + off);
                bh[nj * 2][0] = r4[0]; bh[nj * 2][1] = r4[1];
                bh[nj * 2 + 1][0] = r4[2]; bh[nj * 2 + 1][1] = r4[3];
                if (SPLIT) {
                    LDSM4(r4, sc + OF_BL + off);
                    bl[nj * 2][0] = r4[0]; bl[nj * 2][1] = r4[1];
                    bl[nj * 2 + 1][0] = r4[2]; bl[nj * 2 + 1][1] = r4[3];
                }
            }
#pragma unroll
            for (int mi = 0; mi < 2; mi++)
#pragma unroll
                for (int ni = 0; ni < 8; ni++) {
                    MMA(acc[mi][ni], ah[mi], bh[ni]);
                    if (SPLIT) {
                        MMA(acc[mi][ni], ah[mi], bl[ni]);
                        MMA(acc[mi][ni], al[mi], bh[ni]);
                    }
                }
        }
        __syncthreads();
    }

    // ---------------- epilogue ----------------
    int r_in = lid >> 2, c_in = (lid & 3) << 1;

    if (MODE == 0) {
#pragma unroll
        for (int mi = 0; mi < 2; mi++)
#pragma unroll
            for (int ni = 0; ni < 8; ni++) {
                int rbase = (int)aRow0 + wm * 32 + mi * 16 + r_in;
                int tok = n0 + wn * 64 + ni * 8 + c_in;
#pragma unroll
                for (int hrow = 0; hrow < 2; hrow++) {
                    int r = rbase + hrow * 8;
                    long long off = ((long long)z * 256 + r) * NTP + tok;
                    __nv_bfloat16 h0, l0, h1, l1;
                    split2(acc[mi][ni][hrow * 2],     &h0, &l0);
                    split2(acc[mi][ni][hrow * 2 + 1], &h1, &l1);
                    __nv_bfloat162 ph; ph.x = h0; ph.y = h1;
                    __nv_bfloat162 pl; pl.x = l0; pl.y = l1;
                    *(__nv_bfloat162*)&g_Phi[off] = ph;
                    *(__nv_bfloat162*)&g_Plo[off] = pl;
                }
            }
    } else if (MODE == 1) {
        // write-only fp32 Mc|Ms scratch, tokens 0..512 (+pad to 640)
#pragma unroll
        for (int mi = 0; mi < 2; mi++)
#pragma unroll
            for (int ni = 0; ni < 8; ni++) {
                long long mrow = (long long)z * MIXM + aRow0 + wm * 32 + mi * 16 + r_in;
                int col = n0 + wn * 64 + ni * 8 + c_in;
#pragma unroll
                for (int hrow = 0; hrow < 2; hrow++) {
                    float2 t2;
                    t2.x = acc[mi][ni][hrow * 2];
                    t2.y = acc[mi][ni][hrow * 2 + 1];
                    *(float2*)&g_mix[(mrow + hrow * 8) * ND + col] = t2;
                }
            }
    } else if (MODE == 3) {
#pragma unroll
        for (int mi = 0; mi < 2; mi++)
#pragma unroll
            for (int ni = 0; ni < 8; ni++) {
                long long mrow = aRow0 + wm * 32 + mi * 16 + r_in;
                int col = n0 + wn * 64 + ni * 8 + c_in;
#pragma unroll
                for (int hrow = 0; hrow < 2; hrow++) {
                    float* tp = g_t + (mrow + hrow * 8) * ND + col;
                    float2 t2 = *(float2*)tp;
                    t2.x += acc[mi][ni][hrow * 2]     + x0[col];
                    t2.y += acc[mi][ni][hrow * 2 + 1] + x0[col + 1];
                    *(float2*)tp = t2;
                }
            }
    } else if (MODE == 2) {
#pragma unroll
        for (int mi = 0; mi < 2; mi++)
#pragma unroll
            for (int ni = 0; ni < 8; ni++) {
                long long mrow = aRow0 + wm * 32 + mi * 16 + r_in;
                int col = n0 + wn * 64 + ni * 8 + c_in;
                float bb0 = x0[col], bb1 = x0[col + 1];
#pragma unroll
                for (int hrow = 0; hrow < 2; hrow++) {
                    float v0 = acc[mi][ni][hrow * 2] + bb0;
                    float v1 = acc[mi][ni][hrow * 2 + 1] + bb1;
                    v0 = v0 > 0.f ? v0 : 0.01f * v0;
                    v1 = v1 > 0.f ? v1 : 0.01f * v1;
                    __nv_bfloat162 ph;
                    ph.x = __float2bfloat16(v0);
                    ph.y = __float2bfloat16(v1);
                    *(__nv_bfloat162*)&g_hidhi[(mrow + hrow * 8) * NH + col] = ph;
                }
            }
    } else {  // MODE 4
#pragma unroll
        for (int mi = 0; mi < 2; mi++)
#pragma unroll
            for (int ni = 0; ni < 8; ni++) {
                long long m = aRow0 + wm * 32 + mi * 16 + r_in;
                int col = n0 + wn * 64 + ni * 8 + c_in;
                float cb0 = x0[col], cb1 = x0[col + 1];
#pragma unroll
                for (int hrow = 0; hrow < 2; hrow++) {
                    long long mm = m + hrow * 8;
                    long long b = mm >> 10;
                    int p = (int)(mm & 1023);
                    float* tp = g_t + (b * NTP + 1 + p) * ND + col;
                    const float* pp = x1 + (long long)(1 + p) * ND + col;
                    tp[0] = acc[mi][ni][hrow * 2]     + cb0 + pp[0];
                    tp[1] = acc[mi][ni][hrow * 2 + 1] + cb1 + pp[1];
                }
            }
    }
}

// ---------------- dim-0 mixing: g_mix0 = Cn * u0 (fp32) ----------------
__global__ void gemm0_kernel() {   // grid (NTP/128, NB), block 128
    __shared__ float su[NTP];
    int b = blockIdx.y;
    int t0 = blockIdx.x * 128 + threadIdx.x;
    for (int k = threadIdx.x; k < NTP; k += 128) su[k] = g_u0[b * NTP + k];
    __syncthreads();
    float acc = 0.f;
#pragma unroll 8
    for (int k = 0; k < NTOK; k++)
        acc += g_Cnf[(long long)k * NTP + t0] * su[k];
    g_mix0[b * NTP + t0] = acc;
}

// ---------------- combine: t += symmetric reconstruction (both axes) ----------------
__global__ void combine_kernel() {   // grid (NTOK, NB), block 256
    __shared__ float sh[256];
    int m = blockIdx.x, b = blockIdx.y;
    int ms = (m <= 512) ? m : (NTOK - m);
    float sgn = (m <= 512) ? 1.f : -1.f;
    int d = threadIdx.x;
    sh[d] = g_mix[((long long)b * MIXM + ms) * ND + d];
    __syncthreads();
    float add;
    if (d == 0)        add = g_mix0[(long long)b * NTP + m];
    else if (d <= 128) add = sh[d - 1] - sgn * sh[127 + d];
    else { int dp = 256 - d; add = sh[dp - 1] + sgn * sh[127 + dp]; }
    g_t[((long long)b * NTP + m) * ND + d] += add;
}

// ---------------- fills ----------------
__global__ void fill_bd() {            // grid 256, block 256
    int i = blockIdx.x, j = threadIdx.x;
    int dim = (i & 127) + 1;
    int r = (dim * j) & 255;
    float s, c;
    sincospif(2.0f * (float)r / 256.0f, &s, &c);
    split2(i < 128 ? c : s, &g_Bdhi[i * ND + j], &g_Bdlo[i * ND + j]);
}
__global__ void fill_cn() {            // grid NTP, block 256
    int m = blockIdx.x;
    for (int k = threadIdx.x; k < NTP; k += 256) {
        float vc = 0.f, vs = 0.f;
        if (m < NTOK && k < NTOK) {
            int r = (int)(((long long)m * k) % NTOK);
            sincospif(2.0f * (float)r / (float)NTOK, &vs, &vc);
        }
        long long o = (long long)m * NTP + k;
        split2(vc, &g_Cnh[o], &g_Cnl[o]);
        split2(vs, &g_Snh[o], &g_Snl[o]);
        g_Cnf[o] = vc;
    }
}
__global__ void fill_wp(const float* __restrict__ w) {
    int n = blockIdx.x;
    for (int k = threadIdx.x; k < KPE; k += 256)
        split2(w[(long long)n * KPE + k], &g_wphi[n * KPE + k], &g_wplo[n * KPE + k]);
}
__global__ void fill_w1t(const float* __restrict__ w) {   // grid (NH, L)
    int n = blockIdx.x, i = blockIdx.y, k = threadIdx.x;
    g_w1thi[((long long)i * NH + n) * ND + k] =
        __float2bfloat16(w[((long long)i * ND + k) * NH + n]);
}
__global__ void fill_w2t(const float* __restrict__ w) {   // grid (ND, L)
    int n = blockIdx.x, i = blockIdx.y;
    for (int k = threadIdx.x; k < NH; k += 256)
        g_w2thi[((long long)i * ND + n) * NH + k] =
            __float2bfloat16(w[((long long)i * NH + k) * ND + n]);
}
__global__ void patch_gather(const float* __restrict__ x) {
    int m = blockIdx.x;
    int b = m >> 10, p = m & 1023;
    int gh = p >> 5, gw = p & 31;
    for (int k = threadIdx.x; k < KPE; k += 256) {
        int cch = k >> 8, rem = k & 255, rr = rem >> 4, q = rem & 15;
        float v = x[(((long long)b * 3 + cch) * 512 + gh * 16 + rr) * 512 + gw * 16 + q];
        split2(v, &g_pahi[(long long)m * KPE + k], &g_palo[(long long)m * KPE + k]);
    }
}
__global__ void cls_init(const float* __restrict__ cls, const float* __restrict__ pos) {
    g_t[(long long)blockIdx.x * NTP * ND + threadIdx.x] = cls[threadIdx.x] + pos[threadIdx.x];
}

// ---------------- LN + split (+ rowsum for dim-0 path) ----------------
__device__ __forceinline__ float warp_sum(float v) {
#pragma unroll
    for (int o = 16; o > 0; o >>= 1) v += __shfl_xor_sync(0xffffffffu, v, o);
    return v;
}
__device__ __forceinline__ float warp_max(float v) {
#pragma unroll
    for (int o = 16; o > 0; o >>= 1) v = fmaxf(v, __shfl_xor_sync(0xffffffffu, v, o));
    return v;
}
template<int U0>
__global__ void ln_split(const float* __restrict__ gam, const float* __restrict__ bet) {
    int tid = threadIdx.x, wid = tid >> 5, lane = tid & 31;
    long long row = (long long)blockIdx.x * 8 + wid;
    long long o = row * ND + lane * 8;
    if ((int)(row % NTP) >= NTOK) {
        uint4 zz = make_uint4(0, 0, 0, 0);
        *(uint4*)(g_hhi + o) = zz;
        *(uint4*)(g_hlo + o) = zz;
        if (U0 && lane == 0) g_u0[row] = 0.f;
        return;
    }
    float v[8];
    float4 a = *(const float4*)(g_t + o), b = *(const float4*)(g_t + o + 4);
    v[0]=a.x; v[1]=a.y; v[2]=a.z; v[3]=a.w; v[4]=b.x; v[5]=b.y; v[6]=b.z; v[7]=b.w;
    float s = 0.f;
#pragma unroll
    for (int k = 0; k < 8; k++) s += v[k];
    float mean = warp_sum(s) * (1.f / 256.f);
    float q = 0.f;
#pragma unroll
    for (int k = 0; k < 8; k++) { float d = v[k] - mean; q += d * d; }
    float rstd = rsqrtf(warp_sum(q) * (1.f / 256.f) + 1e-5f);
    float4 g0 = *(const float4*)(gam + lane * 8), g1 = *(const float4*)(gam + lane * 8 + 4);
    float4 b0 = *(const float4*)(bet + lane * 8), b1 = *(const float4*)(bet + lane * 8 + 4);
    float gg[8] = {g0.x,g0.y,g0.z,g0.w,g1.x,g1.y,g1.z,g1.w};
    float bb[8] = {b0.x,b0.y,b0.z,b0.w,b1.x,b1.y,b1.z,b1.w};
    float rs = 0.f;
#pragma unroll
    for (int k = 0; k < 8; k++) {
        float r = (v[k] - mean) * rstd * gg[k] + bb[k];
        if (U0) rs += r;
        split2(r, &g_hhi[o + k], &g_hlo[o + k]);
    }
    if (U0) {
        float tot = warp_sum(rs);
        if (lane == 0) g_u0[row] = tot;
    }
}

// ---------------- pool + head ----------------
__global__ void pool_kernel() {
    int b = blockIdx.x, d = threadIdx.x;
    const float* p = g_t + (long long)b * NTP * ND + d;
    float s = 0.f;
#pragma unroll 8
    for (int n = 0; n < NTOK; n++) s += p[(long long)n * ND];
    g_pooled[b * ND + d] = s * (1.f / 1025.f);
}
__device__ float block_sum(float v, float* sbuf) {
    int tid = threadIdx.x;
    float w = warp_sum(v);
    if ((tid & 31) == 0) sbuf[tid >> 5] = w;
    __syncthreads();
    float r = (tid < 8) ? sbuf[tid] : 0.f;
    if (tid < 32) { r = warp_sum(r); if (tid == 0) sbuf[0] = r; }
    __syncthreads();
    float res = sbuf[0];
    __syncthreads();
    return res;
}
__device__ float block_max(float v, float* sbuf) {
    int tid = threadIdx.x;
    float w = warp_max(v);
    if ((tid & 31) == 0) sbuf[tid >> 5] = w;
    __syncthreads();
    float r = (tid < 8) ? sbuf[tid] : -3.4e38f;
    if (tid < 32) { r = warp_max(r); if (tid == 0) sbuf[0] = r; }
    __syncthreads();
    float res = sbuf[0];
    __syncthreads();
    return res;
}
__global__ void head_kernel(const float* __restrict__ hw, const float* __restrict__ hb,
                            const float* __restrict__ gs, const float* __restrict__ gb,
                            float* __restrict__ out) {
    __shared__ float sbuf[32];
    __shared__ float lnp[256];
    int b = blockIdx.x, tid = threadIdx.x;
    float v = g_pooled[b * ND + tid];
    float mean = block_sum(v, sbuf) * (1.f / 256.f);
    float d = v - mean;
    float var = block_sum(d * d, sbuf) * (1.f / 256.f);
    lnp[tid] = d * rsqrtf(var + 1e-5f) * gs[tid] + gb[tid];
    __syncthreads();
    float lg[4];
#pragma unroll
    for (int j = 0; j < 4; j++) {
        int n = tid + j * 256;
        float s = -3.4e38f;
        if (n < NCLS) {
            s = hb[n];
            for (int k = 0; k < ND; k++) s = fmaf(lnp[k], hw[k * NCLS + n], s);
        }
        lg[j] = s;
    }
    float mx = block_max(fmaxf(fmaxf(lg[0], lg[1]), fmaxf(lg[2], lg[3])), sbuf);
    float es = 0.f;
#pragma unroll
    for (int j = 0; j < 4; j++) {
        int n = tid + j * 256;
        if (n < NCLS) { lg[j] = expf(lg[j] - mx); es += lg[j]; }
    }
    float inv = 1.f / block_sum(es, sbuf);
#pragma unroll
    for (int j = 0; j < 4; j++) {
        int n = tid + j * 256;
        if (n < NCLS) out[(long long)b * NCLS + n] = lg[j] * inv;
    }
}

// ---------------- host ----------------
extern "C" void kernel_launch(void* const* d_in, const int* in_sizes, int n_in,
                              void* d_out, int out_size) {
    const float* x      = (const float*)d_in[0];
    const float* conv_w = (const float*)d_in[1];
    const float* conv_b = (const float*)d_in[2];
    const float* pos    = (const float*)d_in[3];
    const float* cls    = (const float*)d_in[4];
    const float* ln1_s  = (const float*)d_in[5];
    const float* ln1_b  = (const float*)d_in[6];
    const float* ln2_s  = (const float*)d_in[7];
    const float* ln2_b  = (const float*)d_in[8];
    const float* w1     = (const float*)d_in[9];
    const float* b1     = (const float*)d_in[10];
    const float* w2     = (const float*)d_in[11];
    const float* b2     = (const float*)d_in[12];
    const float* hls    = (const float*)d_in[13];
    const float* hlb    = (const float*)d_in[14];
    const float* hw     = (const float*)d_in[15];
    const float* hb     = (const float*)d_in[16];
    float* out = (float*)d_out;

    cudaFuncSetAttribute(gemm_mma<0>, cudaFuncAttributeMaxDynamicSharedMemorySize, CF<0>::DSMB);
    cudaFuncSetAttribute(gemm_mma<1>, cudaFuncAttributeMaxDynamicSharedMemorySize, CF<1>::DSMB);
    cudaFuncSetAttribute(gemm_mma<2>, cudaFuncAttributeMaxDynamicSharedMemorySize, CF<2>::DSMB);
    cudaFuncSetAttribute(gemm_mma<3>, cudaFuncAttributeMaxDynamicSharedMemorySize, CF<3>::DSMB);
    cudaFuncSetAttribute(gemm_mma<4>, cudaFuncAttributeMaxDynamicSharedMemorySize, CF<4>::DSMB);

    fill_bd<<<256, 256>>>();
    fill_cn<<<NTP, 256>>>();
    fill_wp<<<256, 256>>>(conv_w);
    fill_w1t<<<dim3(NH, L), 256>>>(w1);
    fill_w2t<<<dim3(ND, L), 256>>>(w2);
    patch_gather<<<MPE, 256>>>(x);
    cls_init<<<NB, 256>>>(cls, pos);
    gemm_mma<4><<<dim3(MPE / 128, ND / 128, 1), 256, CF<4>::DSMB>>>(conv_b, pos, 0);

    for (int i = 0; i < 6; i++) {
        ln_split<1><<<MROWS / 8, 256>>>(ln1_s + (size_t)i * ND, ln1_b + (size_t)i * ND);
        gemm_mma<0><<<dim3(2, NTP / 128, NB), 256, CF<0>::DSMB>>>(nullptr, nullptr, i);
        gemm_mma<1><<<dim3(MIXM / 128, 2, NB), 256, CF<1>::DSMB>>>(nullptr, nullptr, i);
        gemm0_kernel<<<dim3(NTP / 128, NB), 128>>>();
        combine_kernel<<<dim3(NTOK, NB), 256>>>();
        ln_split<0><<<MROWS / 8, 256>>>(ln2_s + (size_t)i * ND, ln2_b + (size_t)i * ND);
        gemm_mma<2><<<dim3(MROWS / 128, NH / 128, 1), 256, CF<2>::DSMB>>>(b1 + (size_t)i * NH, nullptr, i);
        gemm_mma<3><<<dim3(MROWS / 128, ND / 128, 1), 256, CF<3>::DSMB>>>(b2 + (size_t)i * ND, nullptr, i);
    }

    pool_kernel<<<NB, 256>>>();
    head_kernel<<<NB, 256>>>(hw, hb, hls, hlb, out);
}

// round 16
// speedup vs baseline: 4.5560x; 1.0703x over previous
#include <cuda_runtime.h>
#include <cuda_bf16.h>
#include <cstdint>

#define NTP   1152
#define NTOK  1025
#define ND    256
#define NH    1024
#define NCLS  1000
#define NB    64
#define MROWS (NB*NTP)
#define KPE   768
#define MPE   (NB*1024)
#define L     6
#define MIXM  640            // mix output rows kept: tokens 0..512 (+pad), 5*128
#define KMIXF 640            // folded mix K: tokens 0..512 (+pad), 10*64

// ---------------- static scratch ----------------
__device__ float          g_t    [(long long)MROWS*ND];
__device__ float          g_pooled[NB*ND];
__device__ float          g_mix  [(long long)NB*MIXM*ND];   // Mc|Ms, tokens 0..512
__device__ float          g_mix0 [MROWS];                   // dim-0 mixing result
__device__ float          g_u0   [MROWS];                   // rowsum of LN output
__device__ float          g_Cnf  [(long long)NTP*NTP];      // fp32 cos DFT (symmetric)
__device__ __nv_bfloat16  g_hhi  [(long long)MROWS*ND];
__device__ __nv_bfloat16  g_hlo  [(long long)MROWS*ND];
__device__ __nv_bfloat16  g_Phi  [(long long)NB*256*NTP];   // [b][r:128U+128V][tok]
__device__ __nv_bfloat16  g_Plo  [(long long)NB*256*NTP];
__device__ __nv_bfloat16  g_Pfh  [(long long)NB*256*KMIXF]; // folded P
__device__ __nv_bfloat16  g_Pfl  [(long long)NB*256*KMIXF];
__device__ __nv_bfloat16  g_hidhi[(long long)MROWS*NH];
__device__ __nv_bfloat16  g_Cnh  [(long long)MIXM*KMIXF];
__device__ __nv_bfloat16  g_Cnl  [(long long)MIXM*KMIXF];
__device__ __nv_bfloat16  g_Snh  [(long long)MIXM*KMIXF];
__device__ __nv_bfloat16  g_Snl  [(long long)MIXM*KMIXF];
__device__ __nv_bfloat16  g_Bdhi [256*ND];                  // [Cd d=1..128 ; Sd d=1..128]
__device__ __nv_bfloat16  g_Bdlo [256*ND];
__device__ __nv_bfloat16  g_w1thi[(long long)L*NH*ND];
__device__ __nv_bfloat16  g_w2thi[(long long)L*ND*NH];
__device__ __nv_bfloat16  g_wphi [ND*KPE];
__device__ __nv_bfloat16  g_wplo [ND*KPE];
__device__ __nv_bfloat16  g_pahi [(long long)MPE*KPE];
__device__ __nv_bfloat16  g_palo [(long long)MPE*KPE];

// ---------------- helpers ----------------
__device__ __forceinline__ uint32_t smem_to_u32(const void* p) {
    uint32_t a;
    asm("{ .reg .u64 t; cvta.to.shared.u64 t, %1; cvt.u32.u64 %0, t; }" : "=r"(a) : "l"(p));
    return a;
}
__device__ __forceinline__ void split2(float v, __nv_bfloat16* hi, __nv_bfloat16* lo) {
    __nv_bfloat16 h = __float2bfloat16(v);
    *hi = h;
    *lo = __float2bfloat16(v - __bfloat162float(h));
}

#define LDSM4(r, addr) \
    asm volatile("ldmatrix.sync.aligned.m8n8.x4.shared.b16 {%0,%1,%2,%3}, [%4];" \
                 : "=r"((r)[0]), "=r"((r)[1]), "=r"((r)[2]), "=r"((r)[3]) : "r"(addr))

#define MMA(d, a, b) \
    asm volatile("mma.sync.aligned.m16n8k16.row.col.f32.bf16.bf16.f32 " \
                 "{%0,%1,%2,%3},{%4,%5,%6,%7},{%8,%9},{%0,%1,%2,%3};" \
                 : "+f"((d)[0]), "+f"((d)[1]), "+f"((d)[2]), "+f"((d)[3]) \
                 : "r"((a)[0]), "r"((a)[1]), "r"((a)[2]), "r"((a)[3]), "r"((b)[0]), "r"((b)[1]))

#define CP16(dst, src) \
    asm volatile("cp.async.cg.shared.global [%0], [%1], 16;" :: "r"(dst), "l"(src))
#define CP_COMMIT() asm volatile("cp.async.commit_group;" ::: "memory")
#define CP_WAIT0()  asm volatile("cp.async.wait_group 0;" ::: "memory")
#define CP_WAIT1()  asm volatile("cp.async.wait_group 1;" ::: "memory")

// ---------------- GEMM engine ----------------
// BM=128, BN=128, BK=64; 256 threads, 8 warps (4m x 2n), warp tile 32x64.
// A: [M][K] bf16; B: [N][K] bf16 (K contiguous). D = A*B^T (fp32 accum).
// MODE 0: A=BdN(256x256) B=h[b] -> P (U,V transposed)                [SPLIT]
// MODE 1: A=Cn or Sn rows 0..639 B=Pf half, K=640 -> g_mix (write)   [SPLIT]
// MODE 2: A=h(hi) B=w1t[li] K=256  -> leaky(D+b1) -> hidhi           [plain]
// MODE 3: A=hidhi B=w2t[li] K=1024 -> t += D + b2                    [plain]
// MODE 4: A=pa B=wp K=768 -> t = D + conv_b + pos                    [SPLIT]
#define STR 72
#define TILE_H (128*STR)

template<int MODE> struct CF {
    static constexpr int K     = (MODE == 1) ? KMIXF : (MODE == 3) ? NH : (MODE == 4) ? KPE : ND;
    static constexpr int NCH   = K / 64;
    static constexpr int SPLIT = (MODE == 2 || MODE == 3) ? 0 : 1;
    static constexpr int NTIL  = SPLIT ? 4 : 2;
    static constexpr int STB   = NTIL * TILE_H * 2;
    static constexpr int DSMB  = 2 * STB;
};

__device__ __forceinline__ void load4(uint32_t sbase, const __nv_bfloat16* __restrict__ g,
                                      int K, int k0, int tid) {
#pragma unroll
    for (int i = 0; i < 4; i++) {
        int idx = tid + (i << 8);
        int row = idx >> 3, c8 = (idx & 7) << 3;
        uint32_t d = sbase + (uint32_t)((row * STR + c8) << 1);
        const __nv_bfloat16* gp = g + (long long)row * K + k0 + c8;
        CP16(d, gp);
    }
}

template<int MODE>
__global__ void __launch_bounds__(256, 1)
gemm_mma(const float* __restrict__ x0, const float* __restrict__ x1, int li) {
    constexpr int K = CF<MODE>::K, NCH = CF<MODE>::NCH;
    constexpr int SPLIT = CF<MODE>::SPLIT;
    constexpr int STB = CF<MODE>::STB;
    constexpr uint32_t OF_AH = 0;
    constexpr uint32_t OF_AL = TILE_H * 2;
    constexpr uint32_t OF_BH = (SPLIT ? 2 : 1) * TILE_H * 2;
    constexpr uint32_t OF_BL = 3 * TILE_H * 2;

    extern __shared__ char dsm[];
    uint32_t sb = smem_to_u32(dsm);
    int tid = threadIdx.x, wid = tid >> 5, lid = tid & 31;
    int wm = wid & 3, wn = wid >> 2;
    int n0 = blockIdx.y << 7, z = blockIdx.z;
    long long aRow0 = (long long)blockIdx.x << 7;

    const __nv_bfloat16 *Ahi, *Alo = nullptr, *Bhi, *Blo = nullptr;
    if      (MODE == 0) { Ahi = g_Bdhi + aRow0 * K;  Alo = g_Bdlo + aRow0 * K;
                          long long r = (long long)z * NTP + n0;
                          Bhi = g_hhi + r * K;       Blo = g_hlo + r * K; }
    else if (MODE == 1) { Ahi = (n0 ? g_Snh : g_Cnh) + aRow0 * K;
                          Alo = (n0 ? g_Snl : g_Cnl) + aRow0 * K;
                          long long r = ((long long)z * 256 + n0) * K;
                          Bhi = g_Pfh + r;           Blo = g_Pfl + r; }
    else if (MODE == 2) { Ahi = g_hhi + aRow0 * K;
                          Bhi = g_w1thi + ((long long)li * NH + n0) * K; }
    else if (MODE == 3) { Ahi = g_hidhi + aRow0 * K;
                          Bhi = g_w2thi + ((long long)li * ND + n0) * K; }
    else                { Ahi = g_pahi + aRow0 * K;  Alo = g_palo + aRow0 * K;
                          Bhi = g_wphi + (long long)n0 * K;
                          Blo = g_wplo + (long long)n0 * K; }

    float acc[2][8][4];
#pragma unroll
    for (int i = 0; i < 2; i++)
#pragma unroll
        for (int j = 0; j < 8; j++)
#pragma unroll
            for (int q = 0; q < 4; q++) acc[i][j][q] = 0.f;

    int a_r = lid & 15, a_c = (lid >> 4) << 3;
    int b_grp = lid >> 3, b_w = lid & 7;
    int b_roff = ((b_grp >> 1) << 3) + b_w, b_coff = (b_grp & 1) << 3;

    {
        load4(sb + OF_AH, Ahi, K, 0, tid);
        if (SPLIT) load4(sb + OF_AL, Alo, K, 0, tid);
        load4(sb + OF_BH, Bhi, K, 0, tid);
        if (SPLIT) load4(sb + OF_BL, Blo, K, 0, tid);
        CP_COMMIT();
    }

    for (int c = 0; c < NCH; c++) {
        if (c + 1 < NCH) {
            uint32_t s1 = sb + ((c + 1) & 1) * STB;
            int k0 = (c + 1) << 6;
            load4(s1 + OF_AH, Ahi, K, k0, tid);
            if (SPLIT) load4(s1 + OF_AL, Alo, K, k0, tid);
            load4(s1 + OF_BH, Bhi, K, k0, tid);
            if (SPLIT) load4(s1 + OF_BL, Blo, K, k0, tid);
            CP_COMMIT();
            CP_WAIT1();
        } else {
            CP_WAIT0();
        }
        __syncthreads();
        uint32_t sc = sb + (c & 1) * STB;
#pragma unroll
        for (int ks = 0; ks < 4; ks++) {
            uint32_t ah[2][4], al[2][4], bh[8][2], bl[8][2];
#pragma unroll
            for (int mi = 0; mi < 2; mi++) {
                uint32_t off = (uint32_t)(((wm * 32 + mi * 16 + a_r) * STR + ks * 16 + a_c) << 1);
                LDSM4(ah[mi], sc + OF_AH + off);
                if (SPLIT) LDSM4(al[mi], sc + OF_AL + off);
            }
#pragma unroll
            for (int nj = 0; nj < 4; nj++) {
                uint32_t off = (uint32_t)(((wn * 64 + nj * 16 + b_roff) * STR + ks * 16 + b_coff) << 1);
                uint32_t r4[4];
                LDSM4(r4, sc + OF_BH + off);
                bh[nj * 2][0] = r4[0]; bh[nj * 2][1] = r4[1];
                bh[nj * 2 + 1][0] = r4[2]; bh[nj * 2 + 1][1] = r4[3];
                if (SPLIT) {
                    LDSM4(r4, sc + OF_BL + off);
                    bl[nj * 2][0] = r4[0]; bl[nj * 2][1] = r4[1];
                    bl[nj * 2 + 1][0] = r4[2]; bl[nj * 2 + 1][1] = r4[3];
                }
            }
#pragma unroll
            for (int mi = 0; mi < 2; mi++)
#pragma unroll
                for (int ni = 0; ni < 8; ni++) {
                    MMA(acc[mi][ni], ah[mi], bh[ni]);
                    if (SPLIT) {
                        MMA(acc[mi][ni], ah[mi], bl[ni]);
                        MMA(acc[mi][ni], al[mi], bh[ni]);
                    }
                }
        }
        __syncthreads();
    }

    // ---------------- epilogue ----------------
    int r_in = lid >> 2, c_in = (lid & 3) << 1;

    if (MODE == 0) {
#pragma unroll
        for (int mi = 0; mi < 2; mi++)
#pragma unroll
            for (int ni = 0; ni < 8; ni++) {
                int rbase = (int)aRow0 + wm * 32 + mi * 16 + r_in;
                int tok = n0 + wn * 64 + ni * 8 + c_in;
#pragma unroll
                for (int hrow = 0; hrow < 2; hrow++) {
                    int r = rbase + hrow * 8;
                    long long off = ((long long)z * 256 + r) * NTP + tok;
                    __nv_bfloat16 h0, l0, h1, l1;
                    split2(acc[mi][ni][hrow * 2],     &h0, &l0);
                    split2(acc[mi][ni][hrow * 2 + 1], &h1, &l1);
                    __nv_bfloat162 ph; ph.x = h0; ph.y = h1;
                    __nv_bfloat162 pl; pl.x = l0; pl.y = l1;
                    *(__nv_bfloat162*)&g_Phi[off] = ph;
                    *(__nv_bfloat162*)&g_Plo[off] = pl;
                }
            }
    } else if (MODE == 1) {
        // write-only fp32 Mc|Ms scratch, tokens 0..512 (+pad to 640)
#pragma unroll
        for (int mi = 0; mi < 2; mi++)
#pragma unroll
            for (int ni = 0; ni < 8; ni++) {
                long long mrow = (long long)z * MIXM + aRow0 + wm * 32 + mi * 16 + r_in;
                int col = n0 + wn * 64 + ni * 8 + c_in;
#pragma unroll
                for (int hrow = 0; hrow < 2; hrow++) {
                    float2 t2;
                    t2.x = acc[mi][ni][hrow * 2];
                    t2.y = acc[mi][ni][hrow * 2 + 1];
                    *(float2*)&g_mix[(mrow + hrow * 8) * ND + col] = t2;
                }
            }
    } else if (MODE == 3) {
#pragma unroll
        for (int mi = 0; mi < 2; mi++)
#pragma unroll
            for (int ni = 0; ni < 8; ni++) {
                long long mrow = aRow0 + wm * 32 + mi * 16 + r_in;
                int col = n0 + wn * 64 + ni * 8 + c_in;
#pragma unroll
                for (int hrow = 0; hrow < 2; hrow++) {
                    float* tp = g_t + (mrow + hrow * 8) * ND + col;
                    float2 t2 = *(float2*)tp;
                    t2.x += acc[mi][ni][hrow * 2]     + x0[col];
                    t2.y += acc[mi][ni][hrow * 2 + 1] + x0[col + 1];
                    *(float2*)tp = t2;
                }
            }
    } else if (MODE == 2) {
#pragma unroll
        for (int mi = 0; mi < 2; mi++)
#pragma unroll
            for (int ni = 0; ni < 8; ni++) {
                long long mrow = aRow0 + wm * 32 + mi * 16 + r_in;
                int col = n0 + wn * 64 + ni * 8 + c_in;
                float bb0 = x0[col], bb1 = x0[col + 1];
#pragma unroll
                for (int hrow = 0; hrow < 2; hrow++) {
                    float v0 = acc[mi][ni][hrow * 2] + bb0;
                    float v1 = acc[mi][ni][hrow * 2 + 1] + bb1;
                    v0 = v0 > 0.f ? v0 : 0.01f * v0;
                    v1 = v1 > 0.f ? v1 : 0.01f * v1;
                    __nv_bfloat162 ph;
                    ph.x = __float2bfloat16(v0);
                    ph.y = __float2bfloat16(v1);
                    *(__nv_bfloat162*)&g_hidhi[(mrow + hrow * 8) * NH + col] = ph;
                }
            }
    } else {  // MODE 4
#pragma unroll
        for (int mi = 0; mi < 2; mi++)
#pragma unroll
            for (int ni = 0; ni < 8; ni++) {
                long long m = aRow0 + wm * 32 + mi * 16 + r_in;
                int col = n0 + wn * 64 + ni * 8 + c_in;
                float cb0 = x0[col], cb1 = x0[col + 1];
#pragma unroll
                for (int hrow = 0; hrow < 2; hrow++) {
                    long long mm = m + hrow * 8;
                    long long b = mm >> 10;
                    int p = (int)(mm & 1023);
                    float* tp = g_t + (b * NTP + 1 + p) * ND + col;
                    const float* pp = x1 + (long long)(1 + p) * ND + col;
                    tp[0] = acc[mi][ni][hrow * 2]     + cb0 + pp[0];
                    tp[1] = acc[mi][ni][hrow * 2 + 1] + cb1 + pp[1];
                }
            }
    }
}

// ---------------- fold P along token axis: Pf[k] = P[k] +/- P[1025-k] ----------------
__global__ void fold_kernel() {   // grid (256, NB), block 256
    int r = blockIdx.x, b = blockIdx.y;
    long long src = ((long long)b * 256 + r) * NTP;
    long long dst = ((long long)b * 256 + r) * KMIXF;
    float sg = (r < 128) ? 1.f : -1.f;     // U half: +, V half: -
    for (int k = threadIdx.x; k < KMIXF; k += 256) {
        int km = 1025 - k;                 // k=0 -> pad token 1025 (zero)
        float a  = __bfloat162float(g_Phi[src + k])  + __bfloat162float(g_Plo[src + k]);
        float bb = __bfloat162float(g_Phi[src + km]) + __bfloat162float(g_Plo[src + km]);
        split2(a + sg * bb, &g_Pfh[dst + k], &g_Pfl[dst + k]);
    }
}

// ---------------- dim-0 mixing: g_mix0 = Cn * u0 (fp32) ----------------
__global__ void gemm0_kernel() {   // grid (NTP/128, NB), block 128
    __shared__ float su[NTP];
    int b = blockIdx.y;
    int t0 = blockIdx.x * 128 + threadIdx.x;
    for (int k = threadIdx.x; k < NTP; k += 128) su[k] = g_u0[b * NTP + k];
    __syncthreads();
    float acc = 0.f;
#pragma unroll 8
    for (int k = 0; k < NTOK; k++)
        acc += g_Cnf[(long long)k * NTP + t0] * su[k];
    g_mix0[b * NTP + t0] = acc;
}

// ---------------- combine: t += symmetric reconstruction (both axes) ----------------
__global__ void combine_kernel() {   // grid (NTOK, NB), block 256
    __shared__ float sh[256];
    int m = blockIdx.x, b = blockIdx.y;
    int ms = (m <= 512) ? m : (NTOK - m);
    float sgn = (m <= 512) ? 1.f : -1.f;
    int d = threadIdx.x;
    sh[d] = g_mix[((long long)b * MIXM + ms) * ND + d];
    __syncthreads();
    float add;
    if (d == 0)        add = g_mix0[(long long)b * NTP + m];
    else if (d <= 128) add = sh[d - 1] - sgn * sh[127 + d];
    else { int dp = 256 - d; add = sh[dp - 1] + sgn * sh[127 + dp]; }
    g_t[((long long)b * NTP + m) * ND + d] += add;
}

// ---------------- fills ----------------
__global__ void fill_bd() {            // grid 256, block 256
    int i = blockIdx.x, j = threadIdx.x;
    int dim = (i & 127) + 1;
    int r = (dim * j) & 255;
    float s, c;
    sincospif(2.0f * (float)r / 256.0f, &s, &c);
    split2(i < 128 ? c : s, &g_Bdhi[i * ND + j], &g_Bdlo[i * ND + j]);
}
__global__ void fill_cn() {            // grid NTP, block 256
    int m = blockIdx.x;
    for (int k = threadIdx.x; k < NTP; k += 256) {
        float vc = 0.f, vs = 0.f;
        if (m < NTOK && k < NTOK) {
            int r = (int)(((long long)m * k) % NTOK);
            sincospif(2.0f * (float)r / (float)NTOK, &vs, &vc);
        }
        g_Cnf[(long long)m * NTP + k] = vc;
        if (m < MIXM && k < KMIXF) {
            // folded operands: only k<=512 carries weight; zero the pad
            float wc = (k <= 512) ? vc : 0.f;
            float ws = (k <= 512) ? vs : 0.f;
            long long o = (long long)m * KMIXF + k;
            split2(wc, &g_Cnh[o], &g_Cnl[o]);
            split2(ws, &g_Snh[o], &g_Snl[o]);
        }
    }
}
__global__ void fill_wp(const float* __restrict__ w) {
    int n = blockIdx.x;
    for (int k = threadIdx.x; k < KPE; k += 256)
        split2(w[(long long)n * KPE + k], &g_wphi[n * KPE + k], &g_wplo[n * KPE + k]);
}
__global__ void fill_w1t(const float* __restrict__ w) {   // grid (NH, L)
    int n = blockIdx.x, i = blockIdx.y, k = threadIdx.x;
    g_w1thi[((long long)i * NH + n) * ND + k] =
        __float2bfloat16(w[((long long)i * ND + k) * NH + n]);
}
__global__ void fill_w2t(const float* __restrict__ w) {   // grid (ND, L)
    int n = blockIdx.x, i = blockIdx.y;
    for (int k = threadIdx.x; k < NH; k += 256)
        g_w2thi[((long long)i * ND + n) * NH + k] =
            __float2bfloat16(w[((long long)i * NH + k) * ND + n]);
}
__global__ void patch_gather(const float* __restrict__ x) {
    int m = blockIdx.x;
    int b = m >> 10, p = m & 1023;
    int gh = p >> 5, gw = p & 31;
    for (int k = threadIdx.x; k < KPE; k += 256) {
        int cch = k >> 8, rem = k & 255, rr = rem >> 4, q = rem & 15;
        float v = x[(((long long)b * 3 + cch) * 512 + gh * 16 + rr) * 512 + gw * 16 + q];
        split2(v, &g_pahi[(long long)m * KPE + k], &g_palo[(long long)m * KPE + k]);
    }
}
__global__ void cls_init(const float* __restrict__ cls, const float* __restrict__ pos) {
    g_t[(long long)blockIdx.x * NTP * ND + threadIdx.x] = cls[threadIdx.x] + pos[threadIdx.x];
}

// ---------------- LN + split (+ rowsum for dim-0 path) ----------------
__device__ __forceinline__ float warp_sum(float v) {
#pragma unroll
    for (int o = 16; o > 0; o >>= 1) v += __shfl_xor_sync(0xffffffffu, v, o);
    return v;
}
__device__ __forceinline__ float warp_max(float v) {
#pragma unroll
    for (int o = 16; o > 0; o >>= 1) v = fmaxf(v, __shfl_xor_sync(0xffffffffu, v, o));
    return v;
}
template<int U0>
__global__ void ln_split(const float* __restrict__ gam, const float* __restrict__ bet) {
    int tid = threadIdx.x, wid = tid >> 5, lane = tid & 31;
    long long row = (long long)blockIdx.x * 8 + wid;
    long long o = row * ND + lane * 8;
    if ((int)(row % NTP) >= NTOK) {
        uint4 zz = make_uint4(0, 0, 0, 0);
        *(uint4*)(g_hhi + o) = zz;
        *(uint4*)(g_hlo + o) = zz;
        if (U0 && lane == 0) g_u0[row] = 0.f;
        return;
    }
    float v[8];
    float4 a = *(const float4*)(g_t + o), b = *(const float4*)(g_t + o + 4);
    v[0]=a.x; v[1]=a.y; v[2]=a.z; v[3]=a.w; v[4]=b.x; v[5]=b.y; v[6]=b.z; v[7]=b.w;
    float s = 0.f;
#pragma unroll
    for (int k = 0; k < 8; k++) s += v[k];
    float mean = warp_sum(s) * (1.f / 256.f);
    float q = 0.f;
#pragma unroll
    for (int k = 0; k < 8; k++) { float d = v[k] - mean; q += d * d; }
    float rstd = rsqrtf(warp_sum(q) * (1.f / 256.f) + 1e-5f);
    float4 g0 = *(const float4*)(gam + lane * 8), g1 = *(const float4*)(gam + lane * 8 + 4);
    float4 b0 = *(const float4*)(bet + lane * 8), b1 = *(const float4*)(bet + lane * 8 + 4);
    float gg[8] = {g0.x,g0.y,g0.z,g0.w,g1.x,g1.y,g1.z,g1.w};
    float bb[8] = {b0.x,b0.y,b0.z,b0.w,b1.x,b1.y,b1.z,b1.w};
    float rs = 0.f;
#pragma unroll
    for (int k = 0; k < 8; k++) {
        float r = (v[k] - mean) * rstd * gg[k] + bb[k];
        if (U0) rs += r;
        split2(r, &g_hhi[o + k], &g_hlo[o + k]);
    }
    if (U0) {
        float tot = warp_sum(rs);
        if (lane == 0) g_u0[row] = tot;
    }
}

// ---------------- pool + head ----------------
__global__ void pool_kernel() {
    int b = blockIdx.x, d = threadIdx.x;
    const float* p = g_t + (long long)b * NTP * ND + d;
    float s = 0.f;
#pragma unroll 8
    for (int n = 0; n < NTOK; n++) s += p[(long long)n * ND];
    g_pooled[b * ND + d] = s * (1.f / 1025.f);
}
__device__ float block_sum(float v, float* sbuf) {
    int tid = threadIdx.x;
    float w = warp_sum(v);
    if ((tid & 31) == 0) sbuf[tid >> 5] = w;
    __syncthreads();
    float r = (tid < 8) ? sbuf[tid] : 0.f;
    if (tid < 32) { r = warp_sum(r); if (tid == 0) sbuf[0] = r; }
    __syncthreads();
    float res = sbuf[0];
    __syncthreads();
    return res;
}
__device__ float block_max(float v, float* sbuf) {
    int tid = threadIdx.x;
    float w = warp_max(v);
    if ((tid & 31) == 0) sbuf[tid >> 5] = w;
    __syncthreads();
    float r = (tid < 8) ? sbuf[tid] : -3.4e38f;
    if (tid < 32) { r = warp_max(r); if (tid == 0) sbuf[0] = r; }
    __syncthreads();
    float res = sbuf[0];
    __syncthreads();
    return res;
}
__global__ void head_kernel(const float* __restrict__ hw, const float* __restrict__ hb,
                            const float* __restrict__ gs, const float* __restrict__ gb,
                            float* __restrict__ out) {
    __shared__ float sbuf[32];
    __shared__ float lnp[256];
    int b = blockIdx.x, tid = threadIdx.x;
    float v = g_pooled[b * ND + tid];
    float mean = block_sum(v, sbuf) * (1.f / 256.f);
    float d = v - mean;
    float var = block_sum(d * d, sbuf) * (1.f / 256.f);
    lnp[tid] = d * rsqrtf(var + 1e-5f) * gs[tid] + gb[tid];
    __syncthreads();
    float lg[4];
#pragma unroll
    for (int j = 0; j < 4; j++) {
        int n = tid + j * 256;
        float s = -3.4e38f;
        if (n < NCLS) {
            s = hb[n];
            for (int k = 0; k < ND; k++) s = fmaf(lnp[k], hw[k * NCLS + n], s);
        }
        lg[j] = s;
    }
    float mx = block_max(fmaxf(fmaxf(lg[0], lg[1]), fmaxf(lg[2], lg[3])), sbuf);
    float es = 0.f;
#pragma unroll
    for (int j = 0; j < 4; j++) {
        int n = tid + j * 256;
        if (n < NCLS) { lg[j] = expf(lg[j] - mx); es += lg[j]; }
    }
    float inv = 1.f / block_sum(es, sbuf);
#pragma unroll
    for (int j = 0; j < 4; j++) {
        int n = tid + j * 256;
        if (n < NCLS) out[(long long)b * NCLS + n] = lg[j] * inv;
    }
}

// ---------------- host ----------------
extern "C" void kernel_launch(void* const* d_in, const int* in_sizes, int n_in,
                              void* d_out, int out_size) {
    const float* x      = (const float*)d_in[0];
    const float* conv_w = (const float*)d_in[1];
    const float* conv_b = (const float*)d_in[2];
    const float* pos    = (const float*)d_in[3];
    const float* cls    = (const float*)d_in[4];
    const float* ln1_s  = (const float*)d_in[5];
    const float* ln1_b  = (const float*)d_in[6];
    const float* ln2_s  = (const float*)d_in[7];
    const float* ln2_b  = (const float*)d_in[8];
    const float* w1     = (const float*)d_in[9];
    const float* b1     = (const float*)d_in[10];
    const float* w2     = (const float*)d_in[11];
    const float* b2     = (const float*)d_in[12];
    const float* hls    = (const float*)d_in[13];
    const float* hlb    = (const float*)d_in[14];
    const float* hw     = (const float*)d_in[15];
    const float* hb     = (const float*)d_in[16];
    float* out = (float*)d_out;

    cudaFuncSetAttribute(gemm_mma<0>, cudaFuncAttributeMaxDynamicSharedMemorySize, CF<0>::DSMB);
    cudaFuncSetAttribute(gemm_mma<1>, cudaFuncAttributeMaxDynamicSharedMemorySize, CF<1>::DSMB);
    cudaFuncSetAttribute(gemm_mma<2>, cudaFuncAttributeMaxDynamicSharedMemorySize, CF<2>::DSMB);
    cudaFuncSetAttribute(gemm_mma<3>, cudaFuncAttributeMaxDynamicSharedMemorySize, CF<3>::DSMB);
    cudaFuncSetAttribute(gemm_mma<4>, cudaFuncAttributeMaxDynamicSharedMemorySize, CF<4>::DSMB);

    fill_bd<<<256, 256>>>();
    fill_cn<<<NTP, 256>>>();
    fill_wp<<<256, 256>>>(conv_w);
    fill_w1t<<<dim3(NH, L), 256>>>(w1);
    fill_w2t<<<dim3(ND, L), 256>>>(w2);
    patch_gather<<<MPE, 256>>>(x);
    cls_init<<<NB, 256>>>(cls, pos);
    gemm_mma<4><<<dim3(MPE / 128, ND / 128, 1), 256, CF<4>::DSMB>>>(conv_b, pos, 0);

    for (int i = 0; i < 6; i++) {
        ln_split<1><<<MROWS / 8, 256>>>(ln1_s + (size_t)i * ND, ln1_b + (size_t)i * ND);
        gemm_mma<0><<<dim3(2, NTP / 128, NB), 256, CF<0>::DSMB>>>(nullptr, nullptr, i);
        fold_kernel<<<dim3(256, NB), 256>>>();
        gemm_mma<1><<<dim3(MIXM / 128, 2, NB), 256, CF<1>::DSMB>>>(nullptr, nullptr, i);
        gemm0_kernel<<<dim3(NTP / 128, NB), 128>>>();
        combine_kernel<<<dim3(NTOK, NB), 256>>>();
        ln_split<0><<<MROWS / 8, 256>>>(ln2_s + (size_t)i * ND, ln2_b + (size_t)i * ND);
        gemm_mma<2><<<dim3(MROWS / 128, NH / 128, 1), 256, CF<2>::DSMB>>>(b1 + (size_t)i * NH, nullptr, i);
        gemm_mma<3><<<dim3(MROWS / 128, ND / 128, 1), 256, CF<3>::DSMB>>>(b2 + (size_t)i * ND, nullptr, i);
    }

    pool_kernel<<<NB, 256>>>();
    head_kernel<<<NB, 256>>>(hw, hb, hls, hlb, out);
}